// round 7
// baseline (speedup 1.0000x reference)
#include <cuda_runtime.h>
#include <math.h>
#include <stdint.h>

// ---------------- problem constants ----------------
#define BATCH   16
#define CIN     12
#define TLEN    16352
#define ATOM    64
#define STRIDE  32
#define NA      128
#define LLEN    512
#define NROWS   (BATCH*CIN)
#define NOUT    (BATCH*CIN*TLEN)

// ---------------- scratch (device globals) ----------------
__device__ float g_mean[NROWS];
__device__ float g_std[NROWS];
__device__ float g_xnorm[(size_t)BATCH*CIN*TLEN];
__device__ float g_h[(size_t)BATCH*LLEN*64];
__device__ float g_zraw[(size_t)BATCH*NA*LLEN];
__device__ float g_zq[(size_t)BATCH*NA*LLEN];          // compact z_q, row stride 512
__device__ float g_rectotal[(size_t)BATCH*NA*LLEN];
__device__ float g_w1t[12*64*64];
__device__ float g_w2t[64*128];
__device__ float g_shpnT[(size_t)NA*ATOM*NA];          // [(ia*64+k)*128 + oa]  (== Wc for s=1)
__device__ float g_Wc4[(size_t)4*128*17*128];          // [((r*128+ia)*17+mc)*128+oa]
__device__ float g_Wc2[(size_t)2*128*33*128];
__device__ float g_WdT[(size_t)NA*3*384];
__device__ float g_l1[3];

template<int SEL> __device__ __forceinline__ const float* wc_ptr();
template<> __device__ __forceinline__ const float* wc_ptr<4>() { return g_Wc4; }
template<> __device__ __forceinline__ const float* wc_ptr<2>() { return g_Wc2; }
template<> __device__ __forceinline__ const float* wc_ptr<1>() { return g_shpnT; }

// ================= L1: fused stats+norm + misc preps =================
__global__ __launch_bounds__(256) void fused_prep_kernel(
    const float* __restrict__ x,  const float* __restrict__ w1,
    const float* __restrict__ w2, const float* __restrict__ shp,
    const float* __restrict__ dw)
{
    int bid = blockIdx.x, tid = threadIdx.x;
    if (bid < NROWS) {
        int row = bid;
        const float* p = x + (size_t)row * TLEN;
        float s = 0.f, s2 = 0.f;
        for (int i = tid; i < TLEN; i += 256) { float v = p[i]; s += v; s2 += v*v; }
        __shared__ float sh[256], sh2[256];
        sh[tid] = s; sh2[tid] = s2;
        __syncthreads();
        for (int st = 128; st > 0; st >>= 1) {
            if (tid < st) { sh[tid] += sh[tid+st]; sh2[tid] += sh2[tid+st]; }
            __syncthreads();
        }
        __shared__ float smean, sistd;
        if (tid == 0) {
            float mean = sh[0] / (float)TLEN;
            float var  = sh2[0] / (float)TLEN - mean * mean;
            float sd   = sqrtf(var + 1e-5f);
            g_mean[row] = mean; g_std[row] = sd;
            smean = mean; sistd = 1.f / sd;
        }
        __syncthreads();
        float mean = smean, istd = sistd;
        size_t base = (size_t)row * TLEN;
        for (int i = tid; i < TLEN; i += 256)
            g_xnorm[base + i] = (p[i] - mean) * istd;
    } else {
        int base = (bid - NROWS) * 256 + tid;   // 0..8191
        for (int i = base; i < 64*768; i += 8192) {
            int o = i / 768, ck = i % 768;
            g_w1t[ck*64 + o] = w1[i];
        }
        for (int i = base; i < 128*64; i += 8192) {
            int a = i >> 6, o = i & 63;
            g_w2t[o*128 + a] = w2[i];
        }
        for (int i = base; i < 384*NA*3; i += 8192) {
            int row = i % 384; int rest = i / 384; int m = rest % 3; int na = rest / 3;
            int c = row >> 5, r = row & 31;
            int d = m - 1;
            int klo = 32*d + 31 - r; if (klo < 0) klo = 0;
            int khi = 32*d + 62 - r; if (khi > 63) khi = 63;
            float s = 0.f;
            const float* p = dw + ((size_t)c*NA + na) * ATOM;
            for (int k = klo; k <= khi; k++) s += p[k];
            g_WdT[((size_t)na*3 + m)*384 + row] = s;
        }
        for (int i = base; i < NA*NA; i += 8192) {
            int oa = i >> 7, ia = i & 127;
            const float* p = shp + ((size_t)oa*NA + ia) * ATOM;
            float s = 0.f;
            for (int k = 0; k < ATOM; k++) { float v = p[k]; s += v*v; }
            float inv = 1.f / fmaxf(sqrtf(s), 1e-8f);
            for (int k = 0; k < ATOM; k++)
                g_shpnT[((size_t)ia*ATOM + k)*NA + oa] = p[k] * inv;
        }
        if (base < 3) g_l1[base] = 0.f;
    }
}

// ================= L2: fused stem + collapsed-weight prep =================
__device__ __forceinline__ void wc_compute(float* gW, int S, int KC, int MLO, int i) {
    int oa = i & 127;
    int rest = i >> 7;
    int mc = rest % KC;
    int rest2 = rest / KC;
    int ia = rest2 & 127;
    int r  = rest2 >> 7;
    int m = mc - MLO;
    int klo = S*m + 31 - r;
    int khi = klo + S - 1;
    if (klo < 0) klo = 0;
    if (khi > 63) khi = 63;
    float s = 0.f;
    for (int k = klo; k <= khi; k++)
        s += g_shpnT[((size_t)ia*ATOM + k)*NA + oa];
    gW[i] = s;
}

__global__ __launch_bounds__(256) void fused_stem_kernel(const float* __restrict__ b1) {
    __shared__ float xw[12][576];
    int bid = blockIdx.x, tid = threadIdx.x;
    if (bid < 512) {
        int b = bid >> 5, l0 = (bid & 31) * 16;
        for (int j = tid; j < 12*576; j += 256) {
            int c = j / 576, jj = j % 576;
            int g = 32*l0 - 32 + jj;
            xw[c][jj] = (g >= 0 && g < TLEN) ? g_xnorm[((size_t)b*CIN + c)*TLEN + g] : 0.f;
        }
        __syncthreads();
        int o = tid & 63, lh = tid >> 6;   // lh 0..3, 4 l each
        float acc[4] = {0,0,0,0};
        for (int c = 0; c < 12; c++) {
            #pragma unroll 4
            for (int k = 0; k < 64; k++) {
                float w = g_w1t[(c*64 + k)*64 + o];
                #pragma unroll
                for (int i = 0; i < 4; i++)
                    acc[i] += w * xw[c][32*(lh*4 + i) + k];
            }
        }
        float bo = b1[o];
        #pragma unroll
        for (int i = 0; i < 4; i++) {
            int l = l0 + lh*4 + i;
            g_h[((size_t)b*LLEN + l)*64 + o] = fmaxf(acc[i] + bo, 0.f);
        }
    } else {
        int base = (bid - 512) * 256 + tid;      // 0..131071
        const int N4 = 4*128*17*128;
        const int N2 = 2*128*33*128;
        for (int i = base; i < N4; i += 512*256) wc_compute(g_Wc4, 4, 17, 8,  i);
        for (int i = base; i < N2; i += 512*256) wc_compute(g_Wc2, 2, 33, 16, i);
    }
}

// ================= L3: 1x1 conv + fused s=4 pool + l1[0] =================
__global__ __launch_bounds__(256) void conv1x1_pool4_kernel(const float* __restrict__ b2,
                                                            const float* __restrict__ scale) {
    __shared__ float hsm[64][64];     // reused as reduction buffer at the end
    __shared__ float w2sm[64][128];
    int l0 = blockIdx.x * 64, b = blockIdx.y;
    int tid = threadIdx.x;
    for (int i = tid; i < 4096; i += 256) hsm[i >> 6][i & 63] = g_h[((size_t)b*LLEN + l0)*64 + i];
    for (int i = tid; i < 8192; i += 256) w2sm[i >> 7][i & 127] = g_w2t[i];
    __syncthreads();
    int tx = tid & 31, ty = tid >> 5;
    float acc[4][8];
    #pragma unroll
    for (int m = 0; m < 4; m++)
        #pragma unroll
        for (int n = 0; n < 8; n++) acc[m][n] = 0.f;
    for (int o = 0; o < 64; o++) {
        float4 wv = *(const float4*)&w2sm[o][tx*4];
        #pragma unroll
        for (int n = 0; n < 8; n++) {
            float hv = hsm[ty*8 + n][o];
            acc[0][n] += wv.x * hv; acc[1][n] += wv.y * hv;
            acc[2][n] += wv.z * hv; acc[3][n] += wv.w * hv;
        }
    }
    float sc = scale[0];
    float l1loc = 0.f;
    #pragma unroll
    for (int m = 0; m < 4; m++) {
        int a = tx*4 + m;
        float bb = b2[a];
        size_t rowb = ((size_t)b*NA + a)*LLEN;
        #pragma unroll
        for (int n = 0; n < 8; n++) {
            float v = (acc[m][n] + bb) * sc;
            acc[m][n] = v;
            g_zraw[rowb + l0 + ty*8 + n] = v;
        }
        // s=4 pooling: 8 l's = 2 u-groups of 4 (rec_total == 0 at this stage)
        #pragma unroll
        for (int h = 0; h < 2; h++) {
            float zq = 0.25f * (acc[m][4*h] + acc[m][4*h+1] + acc[m][4*h+2] + acc[m][4*h+3]);
            g_zq[rowb + l0/4 + 2*ty + h] = zq;
            l1loc += fabsf(zq);
        }
    }
    // hsm is dead now; reuse its first 256 floats for the l1 reduction
    __syncthreads();
    float* red = &hsm[0][0];
    red[tid] = l1loc;
    __syncthreads();
    for (int st = 128; st > 0; st >>= 1) {
        if (tid < st) red[tid] += red[tid + st];
        __syncthreads();
    }
    if (tid == 0) atomicAdd(&g_l1[0], red[0]);
}

// ================= pool (scales 2, 1): residual -> compact z_q + l1 =================
__global__ __launch_bounds__(128) void pool_kernel(int s, int idx) {
    int row = blockIdx.x;                 // b*128 + a
    size_t base = (size_t)row * LLEN;
    int nq = LLEN / s;
    float inv = 1.f / (float)s;
    float local = 0.f;
    for (int j = threadIdx.x; j < nq; j += 128) {
        int t0 = j * s;
        float sum = 0.f;
        for (int t = 0; t < s; t++) sum += g_zraw[base + t0 + t] - g_rectotal[base + t0 + t];
        float zq = sum * inv;
        local += fabsf(zq);
        g_zq[base + j] = zq;
    }
    __shared__ float red[128];
    red[threadIdx.x] = local;
    __syncthreads();
    for (int st = 64; st > 0; st >>= 1) {
        if (threadIdx.x < st) red[threadIdx.x] += red[threadIdx.x + st];
        __syncthreads();
    }
    if (threadIdx.x == 0) atomicAdd(&g_l1[idx], red[0]);
}

// ================= collapsed shapelet conv (unique writer, no atomics) =================
// rec_total[b, oa, S*u + r] (+)= sum_{ia, mc} Wc[r][ia][mc][oa] * z_q[b, ia, u + mc - MLO]
// grid (S * LQ/128, 2, 16) = (4, 2, 16); block tile 64 oa x 128 u; K = 128 ia * KC
template<int KC, int S, int MLO, bool FIRST>
__global__ __launch_bounds__(256) void conv_collapsed_kernel() {
    const float* gW = wc_ptr<S>();
    constexpr int G  = (KC + 7) / 8;
    constexpr int ZN = 128 + 8*G + 8;        // covers max window read
    __shared__ float Wsm[KC][64];
    __shared__ float zsm[ZN];
    const int LQ = LLEN / S;
    int r = blockIdx.x % S;
    int u0 = (blockIdx.x / S) * 128;
    int oa_half = blockIdx.y;
    int b = blockIdx.z;
    int tid = threadIdx.x;
    int tx = tid & 15, ty = tid >> 4;        // oa = oa_half*64 + tx*4, u = u0 + ty*8 + n
    float acc[4][8];
    #pragma unroll
    for (int m = 0; m < 4; m++)
        #pragma unroll
        for (int n = 0; n < 8; n++) acc[m][n] = 0.f;

    const float* zrow = g_zq + (size_t)b*NA*LLEN;
    for (int ia = 0; ia < 128; ia++) {
        __syncthreads();
        const float* wp = gW + (((size_t)r*128 + ia)*KC)*128 + oa_half*64;
        for (int i = tid; i < KC*64; i += 256)
            Wsm[i >> 6][i & 63] = wp[(size_t)(i >> 6)*128 + (i & 63)];
        for (int j = tid; j < ZN; j += 256) {
            int uq = u0 - MLO + j;
            zsm[j] = (uq >= 0 && uq < LQ) ? zrow[(size_t)ia*LLEN + uq] : 0.f;
        }
        __syncthreads();
        #pragma unroll
        for (int g = 0; g < G; g++) {
            float zw[15];
            #pragma unroll
            for (int j = 0; j < 15; j++) zw[j] = zsm[ty*8 + g*8 + j];
            #pragma unroll
            for (int m = 0; m < 8; m++) {
                if (g*8 + m < KC) {
                    float4 wv = *(const float4*)&Wsm[g*8 + m][tx*4];
                    #pragma unroll
                    for (int n = 0; n < 8; n++) {
                        float z = zw[m + n];
                        acc[0][n] += wv.x * z; acc[1][n] += wv.y * z;
                        acc[2][n] += wv.z * z; acc[3][n] += wv.w * z;
                    }
                }
            }
        }
    }
    int oa = oa_half*64 + tx*4;
    #pragma unroll
    for (int m = 0; m < 4; m++) {
        float* dst = g_rectotal + ((size_t)b*NA + oa + m)*LLEN + r;
        #pragma unroll
        for (int n = 0; n < 8; n++) {
            size_t off = (size_t)S * (u0 + ty*8 + n);
            if (FIRST) dst[off] = acc[m][n];
            else       dst[off] += acc[m][n];
        }
    }
}

// ================= decoder =================
__global__ __launch_bounds__(256) void decoder_kernel(const float* __restrict__ dec_b,
                                                      float* __restrict__ out) {
    __shared__ float Wsm[4][3][64];
    __shared__ float zsm[4][130];
    int q0 = blockIdx.x * 128;
    int row0 = blockIdx.y * 64;
    int b = blockIdx.z;
    int tid = threadIdx.x, tx = tid & 15, ty = tid >> 4;
    float acc[4][8];
    #pragma unroll
    for (int m = 0; m < 4; m++)
        #pragma unroll
        for (int n = 0; n < 8; n++) acc[m][n] = 0.f;

    for (int na0 = 0; na0 < NA; na0 += 4) {
        __syncthreads();
        for (int i = tid; i < 768; i += 256) {
            int nl = i / 192, rem = i % 192, m = rem / 64, rl = rem % 64;
            Wsm[nl][m][rl] = g_WdT[((size_t)(na0+nl)*3 + m)*384 + row0 + rl];
        }
        for (int i = tid; i < 520; i += 256) {
            int nl = i / 130, j = i % 130;
            int q = q0 - 1 + j;
            zsm[nl][j] = (q >= 0 && q < LLEN) ? g_rectotal[((size_t)b*NA + na0 + nl)*LLEN + q] : 0.f;
        }
        __syncthreads();
        #pragma unroll
        for (int nl = 0; nl < 4; nl++) {
            float z[10];
            #pragma unroll
            for (int j = 0; j < 10; j++) z[j] = zsm[nl][ty*8 + j];
            #pragma unroll
            for (int m = 0; m < 3; m++) {
                float4 wv = *(const float4*)&Wsm[nl][m][tx*4];
                #pragma unroll
                for (int n = 0; n < 8; n++) {
                    float zz = z[n + m];
                    acc[0][n] += wv.x * zz; acc[1][n] += wv.y * zz;
                    acc[2][n] += wv.z * zz; acc[3][n] += wv.w * zz;
                }
            }
        }
    }
    int row = row0 + tx*4;
    int c = row >> 5, r0 = row & 31;
    float sd = g_std[b*CIN + c], mn = g_mean[b*CIN + c], bb = dec_b[c];
    float* ob = out + ((size_t)(b*CIN + c)) * TLEN;
    #pragma unroll
    for (int n = 0; n < 8; n++) {
        int q = q0 + ty*8 + n;
        if (q < 511) {
            float4 v;
            v.x = (acc[0][n] + bb) * sd + mn;
            v.y = (acc[1][n] + bb) * sd + mn;
            v.z = (acc[2][n] + bb) * sd + mn;
            v.w = (acc[3][n] + bb) * sd + mn;
            *(float4*)&ob[q*32 + r0] = v;
        }
    }
}

__global__ void finalize_kernel(float* __restrict__ out) {
    out[NOUT]     = 0.f;
    out[NOUT + 1] = 0.01f * (g_l1[0] / (16.f*128.f*128.f)
                           + g_l1[1] / (16.f*128.f*256.f)
                           + g_l1[2] / (16.f*128.f*512.f));
}

// ================= launch =================
extern "C" void kernel_launch(void* const* d_in, const int* in_sizes, int n_in,
                              void* d_out, int out_size) {
    const float* x   = (const float*)d_in[0];
    const float* w1  = (const float*)d_in[1];
    const float* b1  = (const float*)d_in[2];
    const float* w2  = (const float*)d_in[3];
    const float* b2  = (const float*)d_in[4];
    const float* scl = (const float*)d_in[5];
    const float* shp = (const float*)d_in[6];
    const float* dw  = (const float*)d_in[7];
    const float* db  = (const float*)d_in[8];
    float* out = (float*)d_out;

    fused_prep_kernel<<<NROWS + 32, 256>>>(x, w1, w2, shp, dw);     // 1
    fused_stem_kernel<<<1024, 256>>>(b1);                           // 2
    conv1x1_pool4_kernel<<<dim3(8, BATCH), 256>>>(b2, scl);         // 3
    conv_collapsed_kernel<17, 4, 8,  true ><<<dim3(4, 2, BATCH), 256>>>();  // 4 (profiled)
    pool_kernel<<<BATCH*NA, 128>>>(2, 1);                           // 5
    conv_collapsed_kernel<33, 2, 16, false><<<dim3(4, 2, BATCH), 256>>>();  // 6
    pool_kernel<<<BATCH*NA, 128>>>(1, 2);                           // 7
    conv_collapsed_kernel<64, 1, 31, false><<<dim3(4, 2, BATCH), 256>>>();  // 8
    decoder_kernel<<<dim3(4, 6, BATCH), 256>>>(db, out);            // 9
    if (out_size >= NOUT + 2) finalize_kernel<<<1, 1>>>(out);       // 10
}

// round 9
// speedup vs baseline: 1.3444x; 1.3444x over previous
#include <cuda_runtime.h>
#include <math.h>
#include <stdint.h>

// ---------------- problem constants ----------------
#define BATCH   16
#define CIN     12
#define TLEN    16352
#define ATOM    64
#define STRIDE  32
#define NA      128
#define LLEN    512
#define NROWS   (BATCH*CIN)
#define NOUT    (BATCH*CIN*TLEN)

// ---------------- scratch (device globals) ----------------
__device__ float g_mean[NROWS];
__device__ float g_std[NROWS];
__device__ float g_xnorm[(size_t)BATCH*CIN*TLEN];
__device__ float g_h[(size_t)BATCH*LLEN*64];
__device__ float g_zraw[(size_t)BATCH*NA*LLEN];
__device__ float g_zq[(size_t)BATCH*NA*LLEN];          // compact z_q, row stride 512
__device__ float g_rectotal[(size_t)BATCH*NA*LLEN];
__device__ float g_w1t[12*64*64];
__device__ float g_w2t[64*128];
__device__ float g_shpnT[(size_t)NA*ATOM*NA];          // [(ia*64+k)*128 + oa]  (== Wc for s=1)
__device__ float g_Wc4[(size_t)4*128*17*128];          // [((r*128+ia)*17+mc)*128+oa]
__device__ float g_Wc2[(size_t)2*128*33*128];
__device__ float g_WdT[(size_t)NA*3*384];
__device__ float g_l1[3];

template<int SEL> __device__ __forceinline__ const float* wc_ptr();
template<> __device__ __forceinline__ const float* wc_ptr<4>() { return g_Wc4; }
template<> __device__ __forceinline__ const float* wc_ptr<2>() { return g_Wc2; }
template<> __device__ __forceinline__ const float* wc_ptr<1>() { return g_shpnT; }

// ================= L1: fused stats+norm + misc preps + rectotal zero =================
__global__ __launch_bounds__(256) void fused_prep_kernel(
    const float* __restrict__ x,  const float* __restrict__ w1,
    const float* __restrict__ w2, const float* __restrict__ shp,
    const float* __restrict__ dw)
{
    int bid = blockIdx.x, tid = threadIdx.x;
    if (bid < NROWS) {
        int row = bid;
        const float* p = x + (size_t)row * TLEN;
        float s = 0.f, s2 = 0.f;
        for (int i = tid; i < TLEN; i += 256) { float v = p[i]; s += v; s2 += v*v; }
        __shared__ float sh[256], sh2[256];
        sh[tid] = s; sh2[tid] = s2;
        __syncthreads();
        for (int st = 128; st > 0; st >>= 1) {
            if (tid < st) { sh[tid] += sh[tid+st]; sh2[tid] += sh2[tid+st]; }
            __syncthreads();
        }
        __shared__ float smean, sistd;
        if (tid == 0) {
            float mean = sh[0] / (float)TLEN;
            float var  = sh2[0] / (float)TLEN - mean * mean;
            float sd   = sqrtf(var + 1e-5f);
            g_mean[row] = mean; g_std[row] = sd;
            smean = mean; sistd = 1.f / sd;
        }
        __syncthreads();
        float mean = smean, istd = sistd;
        size_t base = (size_t)row * TLEN;
        for (int i = tid; i < TLEN; i += 256)
            g_xnorm[base + i] = (p[i] - mean) * istd;
    } else {
        int base = (bid - NROWS) * 256 + tid;   // 0..8191
        // zero rec_total (conv kernels accumulate with atomics)
        {
            float4 z4 = make_float4(0.f, 0.f, 0.f, 0.f);
            float4* rt4 = (float4*)g_rectotal;
            for (int i = base; i < (BATCH*NA*LLEN)/4; i += 8192) rt4[i] = z4;
        }
        for (int i = base; i < 64*768; i += 8192) {
            int o = i / 768, ck = i % 768;
            g_w1t[ck*64 + o] = w1[i];
        }
        for (int i = base; i < 128*64; i += 8192) {
            int a = i >> 6, o = i & 63;
            g_w2t[o*128 + a] = w2[i];
        }
        for (int i = base; i < 384*NA*3; i += 8192) {
            int row = i % 384; int rest = i / 384; int m = rest % 3; int na = rest / 3;
            int c = row >> 5, r = row & 31;
            int d = m - 1;
            int klo = 32*d + 31 - r; if (klo < 0) klo = 0;
            int khi = 32*d + 62 - r; if (khi > 63) khi = 63;
            float s = 0.f;
            const float* p = dw + ((size_t)c*NA + na) * ATOM;
            for (int k = klo; k <= khi; k++) s += p[k];
            g_WdT[((size_t)na*3 + m)*384 + row] = s;
        }
        for (int i = base; i < NA*NA; i += 8192) {
            int oa = i >> 7, ia = i & 127;
            const float* p = shp + ((size_t)oa*NA + ia) * ATOM;
            float s = 0.f;
            for (int k = 0; k < ATOM; k++) { float v = p[k]; s += v*v; }
            float inv = 1.f / fmaxf(sqrtf(s), 1e-8f);
            for (int k = 0; k < ATOM; k++)
                g_shpnT[((size_t)ia*ATOM + k)*NA + oa] = p[k] * inv;
        }
        if (base < 3) g_l1[base] = 0.f;
    }
}

// ================= L2: fused stem + collapsed-weight prep =================
__device__ __forceinline__ void wc_compute(float* gW, int S, int KC, int MLO, int i) {
    int oa = i & 127;
    int rest = i >> 7;
    int mc = rest % KC;
    int rest2 = rest / KC;
    int ia = rest2 & 127;
    int r  = rest2 >> 7;
    int m = mc - MLO;
    int klo = S*m + 31 - r;
    int khi = klo + S - 1;
    if (klo < 0) klo = 0;
    if (khi > 63) khi = 63;
    float s = 0.f;
    for (int k = klo; k <= khi; k++)
        s += g_shpnT[((size_t)ia*ATOM + k)*NA + oa];
    gW[i] = s;
}

__global__ __launch_bounds__(256) void fused_stem_kernel(const float* __restrict__ b1) {
    __shared__ float xw[12][576];
    int bid = blockIdx.x, tid = threadIdx.x;
    if (bid < 512) {
        int b = bid >> 5, l0 = (bid & 31) * 16;
        for (int j = tid; j < 12*576; j += 256) {
            int c = j / 576, jj = j % 576;
            int g = 32*l0 - 32 + jj;
            xw[c][jj] = (g >= 0 && g < TLEN) ? g_xnorm[((size_t)b*CIN + c)*TLEN + g] : 0.f;
        }
        __syncthreads();
        int o = tid & 63, lh = tid >> 6;   // lh 0..3, 4 l each
        float acc[4] = {0,0,0,0};
        for (int c = 0; c < 12; c++) {
            #pragma unroll 4
            for (int k = 0; k < 64; k++) {
                float w = g_w1t[(c*64 + k)*64 + o];
                #pragma unroll
                for (int i = 0; i < 4; i++)
                    acc[i] += w * xw[c][32*(lh*4 + i) + k];
            }
        }
        float bo = b1[o];
        #pragma unroll
        for (int i = 0; i < 4; i++) {
            int l = l0 + lh*4 + i;
            g_h[((size_t)b*LLEN + l)*64 + o] = fmaxf(acc[i] + bo, 0.f);
        }
    } else {
        int base = (bid - 512) * 256 + tid;      // 0..131071
        const int N4 = 4*128*17*128;
        const int N2 = 2*128*33*128;
        for (int i = base; i < N4; i += 512*256) wc_compute(g_Wc4, 4, 17, 8,  i);
        for (int i = base; i < N2; i += 512*256) wc_compute(g_Wc2, 2, 33, 16, i);
    }
}

// ================= L3: 1x1 conv + fused s=4 pool + l1[0] =================
__global__ __launch_bounds__(256) void conv1x1_pool4_kernel(const float* __restrict__ b2,
                                                            const float* __restrict__ scale) {
    __shared__ float hsm[64][64];     // reused as reduction buffer at the end
    __shared__ float w2sm[64][128];
    int l0 = blockIdx.x * 64, b = blockIdx.y;
    int tid = threadIdx.x;
    for (int i = tid; i < 4096; i += 256) hsm[i >> 6][i & 63] = g_h[((size_t)b*LLEN + l0)*64 + i];
    for (int i = tid; i < 8192; i += 256) w2sm[i >> 7][i & 127] = g_w2t[i];
    __syncthreads();
    int tx = tid & 31, ty = tid >> 5;
    float acc[4][8];
    #pragma unroll
    for (int m = 0; m < 4; m++)
        #pragma unroll
        for (int n = 0; n < 8; n++) acc[m][n] = 0.f;
    for (int o = 0; o < 64; o++) {
        float4 wv = *(const float4*)&w2sm[o][tx*4];
        #pragma unroll
        for (int n = 0; n < 8; n++) {
            float hv = hsm[ty*8 + n][o];
            acc[0][n] += wv.x * hv; acc[1][n] += wv.y * hv;
            acc[2][n] += wv.z * hv; acc[3][n] += wv.w * hv;
        }
    }
    float sc = scale[0];
    float l1loc = 0.f;
    #pragma unroll
    for (int m = 0; m < 4; m++) {
        int a = tx*4 + m;
        float bb = b2[a];
        size_t rowb = ((size_t)b*NA + a)*LLEN;
        #pragma unroll
        for (int n = 0; n < 8; n++) {
            float v = (acc[m][n] + bb) * sc;
            acc[m][n] = v;
            g_zraw[rowb + l0 + ty*8 + n] = v;
        }
        #pragma unroll
        for (int h = 0; h < 2; h++) {
            float zq = 0.25f * (acc[m][4*h] + acc[m][4*h+1] + acc[m][4*h+2] + acc[m][4*h+3]);
            g_zq[rowb + l0/4 + 2*ty + h] = zq;
            l1loc += fabsf(zq);
        }
    }
    __syncthreads();
    float* red = &hsm[0][0];
    red[tid] = l1loc;
    __syncthreads();
    for (int st = 128; st > 0; st >>= 1) {
        if (tid < st) red[tid] += red[tid + st];
        __syncthreads();
    }
    if (tid == 0) atomicAdd(&g_l1[0], red[0]);
}

// ================= pool (scales 2, 1): residual -> compact z_q + l1 =================
__global__ __launch_bounds__(128) void pool_kernel(int s, int idx) {
    int row = blockIdx.x;                 // b*128 + a
    size_t base = (size_t)row * LLEN;
    int nq = LLEN / s;
    float inv = 1.f / (float)s;
    float local = 0.f;
    for (int j = threadIdx.x; j < nq; j += 128) {
        int t0 = j * s;
        float sum = 0.f;
        for (int t = 0; t < s; t++) sum += g_zraw[base + t0 + t] - g_rectotal[base + t0 + t];
        float zq = sum * inv;
        local += fabsf(zq);
        g_zq[base + j] = zq;
    }
    __shared__ float red[128];
    red[threadIdx.x] = local;
    __syncthreads();
    for (int st = 64; st > 0; st >>= 1) {
        if (threadIdx.x < st) red[threadIdx.x] += red[threadIdx.x + st];
        __syncthreads();
    }
    if (threadIdx.x == 0) atomicAdd(&g_l1[idx], red[0]);
}

// ================= collapsed shapelet conv =================
// rec_total[b, oa, S*u + r] += sum_{ia, mc} Wc[r][ia][mc][oa] * z_q[b, ia, u + mc - MLO]
// grid (4, 4 = ia_half*2 + oa_half, 16); block tile 64 oa x 128 u; K-half = 64 ia * KC
// ia chunked 2 per barrier; taps in groups of 4 (zw[11] window) to stay under reg cap.
template<int KC, int S, int MLO>
__global__ __launch_bounds__(256) void conv_collapsed_kernel() {
    const float* gW = wc_ptr<S>();
    constexpr int GF = KC / 4;               // full 4-tap groups
    constexpr int ZN = 128 + KC + 8;
    __shared__ float Wsm[2][KC][64];
    __shared__ float zsm[2][ZN];
    const int LQ = LLEN / S;
    int r = blockIdx.x % S;
    int u0 = (blockIdx.x / S) * 128;
    int oa_half = blockIdx.y & 1, ia_half = blockIdx.y >> 1;
    int b = blockIdx.z;
    int tid = threadIdx.x;
    int tx = tid & 15, ty = tid >> 4;        // oa = oa_half*64 + tx*4, u = u0 + ty*8 + n
    float acc[4][8];
    #pragma unroll
    for (int m = 0; m < 4; m++)
        #pragma unroll
        for (int n = 0; n < 8; n++) acc[m][n] = 0.f;

    const float* zbase = g_zq + ((size_t)b*NA + ia_half*64) * LLEN;
    const float* wbase = gW + ((size_t)r*128 + ia_half*64) * KC * 128 + oa_half*64;

    for (int i0 = 0; i0 < 64; i0 += 2) {
        __syncthreads();
        // weights: 2 ia x KC x 16 float4 (oa-contiguous)
        for (int i = tid; i < 2*KC*16; i += 256) {
            int c = i / (KC*16), rem = i % (KC*16), mc = rem >> 4, q = rem & 15;
            *(float4*)&Wsm[c][mc][q*4] =
                *(const float4*)&wbase[((size_t)(i0 + c)*KC + mc)*128 + q*4];
        }
        // z: 2 x ZN
        for (int j = tid; j < 2*ZN; j += 256) {
            int c = j / ZN, jj = j % ZN;
            int uq = u0 - MLO + jj;
            zsm[c][jj] = (uq >= 0 && uq < LQ) ? zbase[(size_t)(i0 + c)*LLEN + uq] : 0.f;
        }
        __syncthreads();
        for (int c = 0; c < 2; c++) {
            for (int g = 0; g < GF; g++) {
                float zw[11];
                #pragma unroll
                for (int j = 0; j < 11; j++) zw[j] = zsm[c][ty*8 + g*4 + j];
                #pragma unroll
                for (int m = 0; m < 4; m++) {
                    float4 wv = *(const float4*)&Wsm[c][g*4 + m][tx*4];
                    #pragma unroll
                    for (int n = 0; n < 8; n++) {
                        float z = zw[m + n];
                        acc[0][n] += wv.x * z; acc[1][n] += wv.y * z;
                        acc[2][n] += wv.z * z; acc[3][n] += wv.w * z;
                    }
                }
            }
            if constexpr ((KC % 4) != 0) {
                // tail taps (KC%4 of them, KC%4 is 1 for KC=17,33)
                #pragma unroll
                for (int m = GF*4; m < KC; m++) {
                    float zw[8];
                    #pragma unroll
                    for (int j = 0; j < 8; j++) zw[j] = zsm[c][ty*8 + m + j];
                    float4 wv = *(const float4*)&Wsm[c][m][tx*4];
                    #pragma unroll
                    for (int n = 0; n < 8; n++) {
                        float z = zw[n];
                        acc[0][n] += wv.x * z; acc[1][n] += wv.y * z;
                        acc[2][n] += wv.z * z; acc[3][n] += wv.w * z;
                    }
                }
            }
        }
    }
    int oa = oa_half*64 + tx*4;
    #pragma unroll
    for (int m = 0; m < 4; m++) {
        float* dst = g_rectotal + ((size_t)b*NA + oa + m)*LLEN + r;
        #pragma unroll
        for (int n = 0; n < 8; n++)
            atomicAdd(&dst[(size_t)S*(u0 + ty*8 + n)], acc[m][n]);
    }
}

// ================= decoder =================
__global__ __launch_bounds__(256) void decoder_kernel(const float* __restrict__ dec_b,
                                                      float* __restrict__ out) {
    __shared__ float Wsm[4][3][64];
    __shared__ float zsm[4][130];
    int q0 = blockIdx.x * 128;
    int row0 = blockIdx.y * 64;
    int b = blockIdx.z;
    int tid = threadIdx.x, tx = tid & 15, ty = tid >> 4;
    float acc[4][8];
    #pragma unroll
    for (int m = 0; m < 4; m++)
        #pragma unroll
        for (int n = 0; n < 8; n++) acc[m][n] = 0.f;

    for (int na0 = 0; na0 < NA; na0 += 4) {
        __syncthreads();
        for (int i = tid; i < 768; i += 256) {
            int nl = i / 192, rem = i % 192, m = rem / 64, rl = rem % 64;
            Wsm[nl][m][rl] = g_WdT[((size_t)(na0+nl)*3 + m)*384 + row0 + rl];
        }
        for (int i = tid; i < 520; i += 256) {
            int nl = i / 130, j = i % 130;
            int q = q0 - 1 + j;
            zsm[nl][j] = (q >= 0 && q < LLEN) ? g_rectotal[((size_t)b*NA + na0 + nl)*LLEN + q] : 0.f;
        }
        __syncthreads();
        #pragma unroll
        for (int nl = 0; nl < 4; nl++) {
            float z[10];
            #pragma unroll
            for (int j = 0; j < 10; j++) z[j] = zsm[nl][ty*8 + j];
            #pragma unroll
            for (int m = 0; m < 3; m++) {
                float4 wv = *(const float4*)&Wsm[nl][m][tx*4];
                #pragma unroll
                for (int n = 0; n < 8; n++) {
                    float zz = z[n + m];
                    acc[0][n] += wv.x * zz; acc[1][n] += wv.y * zz;
                    acc[2][n] += wv.z * zz; acc[3][n] += wv.w * zz;
                }
            }
        }
    }
    int row = row0 + tx*4;
    int c = row >> 5, r0 = row & 31;
    float sd = g_std[b*CIN + c], mn = g_mean[b*CIN + c], bb = dec_b[c];
    float* ob = out + ((size_t)(b*CIN + c)) * TLEN;
    #pragma unroll
    for (int n = 0; n < 8; n++) {
        int q = q0 + ty*8 + n;
        if (q < 511) {
            float4 v;
            v.x = (acc[0][n] + bb) * sd + mn;
            v.y = (acc[1][n] + bb) * sd + mn;
            v.z = (acc[2][n] + bb) * sd + mn;
            v.w = (acc[3][n] + bb) * sd + mn;
            *(float4*)&ob[q*32 + r0] = v;
        }
    }
}

__global__ void finalize_kernel(float* __restrict__ out) {
    out[NOUT]     = 0.f;
    out[NOUT + 1] = 0.01f * (g_l1[0] / (16.f*128.f*128.f)
                           + g_l1[1] / (16.f*128.f*256.f)
                           + g_l1[2] / (16.f*128.f*512.f));
}

// ================= launch =================
extern "C" void kernel_launch(void* const* d_in, const int* in_sizes, int n_in,
                              void* d_out, int out_size) {
    const float* x   = (const float*)d_in[0];
    const float* w1  = (const float*)d_in[1];
    const float* b1  = (const float*)d_in[2];
    const float* w2  = (const float*)d_in[3];
    const float* b2  = (const float*)d_in[4];
    const float* scl = (const float*)d_in[5];
    const float* shp = (const float*)d_in[6];
    const float* dw  = (const float*)d_in[7];
    const float* db  = (const float*)d_in[8];
    float* out = (float*)d_out;

    fused_prep_kernel<<<NROWS + 32, 256>>>(x, w1, w2, shp, dw);     // 1
    fused_stem_kernel<<<1024, 256>>>(b1);                           // 2
    conv1x1_pool4_kernel<<<dim3(8, BATCH), 256>>>(b2, scl);         // 3
    conv_collapsed_kernel<17, 4, 8 ><<<dim3(4, 4, BATCH), 256>>>(); // 4 (profiled)
    pool_kernel<<<BATCH*NA, 128>>>(2, 1);                           // 5
    conv_collapsed_kernel<33, 2, 16><<<dim3(4, 4, BATCH), 256>>>(); // 6
    pool_kernel<<<BATCH*NA, 128>>>(1, 2);                           // 7
    conv_collapsed_kernel<64, 1, 31><<<dim3(4, 4, BATCH), 256>>>(); // 8
    decoder_kernel<<<dim3(4, 6, BATCH), 256>>>(db, out);            // 9
    if (out_size >= NOUT + 2) finalize_kernel<<<1, 1>>>(out);       // 10
}

// round 10
// speedup vs baseline: 1.4820x; 1.1024x over previous
#include <cuda_runtime.h>
#include <math.h>
#include <stdint.h>

// ---------------- problem constants ----------------
#define BATCH   16
#define CIN     12
#define TLEN    16352
#define ATOM    64
#define STRIDE  32
#define NA      128
#define LLEN    512
#define NROWS   (BATCH*CIN)
#define NOUT    (BATCH*CIN*TLEN)

// ---------------- scratch (device globals) ----------------
__device__ float g_mean[NROWS];
__device__ float g_std[NROWS];
__device__ float g_xnorm[(size_t)BATCH*CIN*TLEN];
__device__ float g_h[(size_t)BATCH*LLEN*64];
__device__ float g_zraw[(size_t)BATCH*NA*LLEN];
__device__ float g_zq[(size_t)BATCH*NA*LLEN];          // compact z_q, row stride 512
__device__ float g_rectotal[(size_t)BATCH*NA*LLEN];
__device__ float g_w1t[12*64*64];
__device__ float g_w2t[64*128];
__device__ float g_shpnT[(size_t)NA*ATOM*NA];          // [(ia*64+k)*128 + oa]  (== Wc for s=1)
__device__ float g_Wc4[(size_t)4*128*17*128];          // [((r*128+ia)*17+mc)*128+oa]
__device__ float g_Wc2[(size_t)2*128*33*128];
__device__ float g_WdT[(size_t)NA*3*384];
__device__ float g_l1[3];

template<int SEL> __device__ __forceinline__ const float* wc_ptr();
template<> __device__ __forceinline__ const float* wc_ptr<4>() { return g_Wc4; }
template<> __device__ __forceinline__ const float* wc_ptr<2>() { return g_Wc2; }
template<> __device__ __forceinline__ const float* wc_ptr<1>() { return g_shpnT; }

// ================= L1: fused stats+norm + misc preps + rectotal zero =================
__global__ __launch_bounds__(256) void fused_prep_kernel(
    const float* __restrict__ x,  const float* __restrict__ w1,
    const float* __restrict__ w2, const float* __restrict__ shp,
    const float* __restrict__ dw)
{
    int bid = blockIdx.x, tid = threadIdx.x;
    if (bid < NROWS) {
        int row = bid;
        const float* p = x + (size_t)row * TLEN;
        float s = 0.f, s2 = 0.f;
        for (int i = tid; i < TLEN; i += 256) { float v = p[i]; s += v; s2 += v*v; }
        __shared__ float sh[256], sh2[256];
        sh[tid] = s; sh2[tid] = s2;
        __syncthreads();
        for (int st = 128; st > 0; st >>= 1) {
            if (tid < st) { sh[tid] += sh[tid+st]; sh2[tid] += sh2[tid+st]; }
            __syncthreads();
        }
        __shared__ float smean, sistd;
        if (tid == 0) {
            float mean = sh[0] / (float)TLEN;
            float var  = sh2[0] / (float)TLEN - mean * mean;
            float sd   = sqrtf(var + 1e-5f);
            g_mean[row] = mean; g_std[row] = sd;
            smean = mean; sistd = 1.f / sd;
        }
        __syncthreads();
        float mean = smean, istd = sistd;
        size_t base = (size_t)row * TLEN;
        for (int i = tid; i < TLEN; i += 256)
            g_xnorm[base + i] = (p[i] - mean) * istd;
    } else {
        int base = (bid - NROWS) * 256 + tid;   // 0..8191
        // zero rec_total (conv kernels accumulate with atomics)
        {
            float4 z4 = make_float4(0.f, 0.f, 0.f, 0.f);
            float4* rt4 = (float4*)g_rectotal;
            for (int i = base; i < (BATCH*NA*LLEN)/4; i += 8192) rt4[i] = z4;
        }
        for (int i = base; i < 64*768; i += 8192) {
            int o = i / 768, ck = i % 768;
            g_w1t[ck*64 + o] = w1[i];
        }
        for (int i = base; i < 128*64; i += 8192) {
            int a = i >> 6, o = i & 63;
            g_w2t[o*128 + a] = w2[i];
        }
        for (int i = base; i < 384*NA*3; i += 8192) {
            int row = i % 384; int rest = i / 384; int m = rest % 3; int na = rest / 3;
            int c = row >> 5, r = row & 31;
            int d = m - 1;
            int klo = 32*d + 31 - r; if (klo < 0) klo = 0;
            int khi = 32*d + 62 - r; if (khi > 63) khi = 63;
            float s = 0.f;
            const float* p = dw + ((size_t)c*NA + na) * ATOM;
            for (int k = klo; k <= khi; k++) s += p[k];
            g_WdT[((size_t)na*3 + m)*384 + row] = s;
        }
        for (int i = base; i < NA*NA; i += 8192) {
            int oa = i >> 7, ia = i & 127;
            const float* p = shp + ((size_t)oa*NA + ia) * ATOM;
            float s = 0.f;
            for (int k = 0; k < ATOM; k++) { float v = p[k]; s += v*v; }
            float inv = 1.f / fmaxf(sqrtf(s), 1e-8f);
            for (int k = 0; k < ATOM; k++)
                g_shpnT[((size_t)ia*ATOM + k)*NA + oa] = p[k] * inv;
        }
        if (base < 3) g_l1[base] = 0.f;
    }
}

// ================= L2: fused stem + collapsed-weight prep =================
__device__ __forceinline__ void wc_compute(float* gW, int S, int KC, int MLO, int i) {
    int oa = i & 127;
    int rest = i >> 7;
    int mc = rest % KC;
    int rest2 = rest / KC;
    int ia = rest2 & 127;
    int r  = rest2 >> 7;
    int m = mc - MLO;
    int klo = S*m + 31 - r;
    int khi = klo + S - 1;
    if (klo < 0) klo = 0;
    if (khi > 63) khi = 63;
    float s = 0.f;
    for (int k = klo; k <= khi; k++)
        s += g_shpnT[((size_t)ia*ATOM + k)*NA + oa];
    gW[i] = s;
}

__global__ __launch_bounds__(256) void fused_stem_kernel(const float* __restrict__ b1) {
    __shared__ float xw[12][576];
    int bid = blockIdx.x, tid = threadIdx.x;
    if (bid < 512) {
        int b = bid >> 5, l0 = (bid & 31) * 16;
        for (int j = tid; j < 12*576; j += 256) {
            int c = j / 576, jj = j % 576;
            int g = 32*l0 - 32 + jj;
            xw[c][jj] = (g >= 0 && g < TLEN) ? g_xnorm[((size_t)b*CIN + c)*TLEN + g] : 0.f;
        }
        __syncthreads();
        int o = tid & 63, lh = tid >> 6;   // lh 0..3, 4 l each
        float acc[4] = {0,0,0,0};
        for (int c = 0; c < 12; c++) {
            #pragma unroll 4
            for (int k = 0; k < 64; k++) {
                float w = g_w1t[(c*64 + k)*64 + o];
                #pragma unroll
                for (int i = 0; i < 4; i++)
                    acc[i] += w * xw[c][32*(lh*4 + i) + k];
            }
        }
        float bo = b1[o];
        #pragma unroll
        for (int i = 0; i < 4; i++) {
            int l = l0 + lh*4 + i;
            g_h[((size_t)b*LLEN + l)*64 + o] = fmaxf(acc[i] + bo, 0.f);
        }
    } else {
        int base = (bid - 512) * 256 + tid;      // 0..131071
        const int N4 = 4*128*17*128;
        const int N2 = 2*128*33*128;
        for (int i = base; i < N4; i += 512*256) wc_compute(g_Wc4, 4, 17, 8,  i);
        for (int i = base; i < N2; i += 512*256) wc_compute(g_Wc2, 2, 33, 16, i);
    }
}

// ================= L3: 1x1 conv + fused s=4 pool + l1[0] =================
__global__ __launch_bounds__(256) void conv1x1_pool4_kernel(const float* __restrict__ b2,
                                                            const float* __restrict__ scale) {
    __shared__ float hsm[64][64];     // reused as reduction buffer at the end
    __shared__ float w2sm[64][128];
    int l0 = blockIdx.x * 64, b = blockIdx.y;
    int tid = threadIdx.x;
    for (int i = tid; i < 4096; i += 256) hsm[i >> 6][i & 63] = g_h[((size_t)b*LLEN + l0)*64 + i];
    for (int i = tid; i < 8192; i += 256) w2sm[i >> 7][i & 127] = g_w2t[i];
    __syncthreads();
    int tx = tid & 31, ty = tid >> 5;
    float acc[4][8];
    #pragma unroll
    for (int m = 0; m < 4; m++)
        #pragma unroll
        for (int n = 0; n < 8; n++) acc[m][n] = 0.f;
    for (int o = 0; o < 64; o++) {
        float4 wv = *(const float4*)&w2sm[o][tx*4];
        #pragma unroll
        for (int n = 0; n < 8; n++) {
            float hv = hsm[ty*8 + n][o];
            acc[0][n] += wv.x * hv; acc[1][n] += wv.y * hv;
            acc[2][n] += wv.z * hv; acc[3][n] += wv.w * hv;
        }
    }
    float sc = scale[0];
    float l1loc = 0.f;
    #pragma unroll
    for (int m = 0; m < 4; m++) {
        int a = tx*4 + m;
        float bb = b2[a];
        size_t rowb = ((size_t)b*NA + a)*LLEN;
        #pragma unroll
        for (int n = 0; n < 8; n++) {
            float v = (acc[m][n] + bb) * sc;
            acc[m][n] = v;
            g_zraw[rowb + l0 + ty*8 + n] = v;
        }
        #pragma unroll
        for (int h = 0; h < 2; h++) {
            float zq = 0.25f * (acc[m][4*h] + acc[m][4*h+1] + acc[m][4*h+2] + acc[m][4*h+3]);
            g_zq[rowb + l0/4 + 2*ty + h] = zq;
            l1loc += fabsf(zq);
        }
    }
    __syncthreads();
    float* red = &hsm[0][0];
    red[tid] = l1loc;
    __syncthreads();
    for (int st = 128; st > 0; st >>= 1) {
        if (tid < st) red[tid] += red[tid + st];
        __syncthreads();
    }
    if (tid == 0) atomicAdd(&g_l1[0], red[0]);
}

// ================= pool (scales 2, 1): residual -> compact z_q + l1 =================
__global__ __launch_bounds__(128) void pool_kernel(int s, int idx) {
    int row = blockIdx.x;                 // b*128 + a
    size_t base = (size_t)row * LLEN;
    int nq = LLEN / s;
    float inv = 1.f / (float)s;
    float local = 0.f;
    for (int j = threadIdx.x; j < nq; j += 128) {
        int t0 = j * s;
        float sum = 0.f;
        for (int t = 0; t < s; t++) sum += g_zraw[base + t0 + t] - g_rectotal[base + t0 + t];
        float zq = sum * inv;
        local += fabsf(zq);
        g_zq[base + j] = zq;
    }
    __shared__ float red[128];
    red[threadIdx.x] = local;
    __syncthreads();
    for (int st = 64; st > 0; st >>= 1) {
        if (threadIdx.x < st) red[threadIdx.x] += red[threadIdx.x + st];
        __syncthreads();
    }
    if (threadIdx.x == 0) atomicAdd(&g_l1[idx], red[0]);
}

// ================= collapsed shapelet conv =================
// rec_total[b, oa, S*u + r] += sum_{ia, mc} Wc[r][ia][mc][oa] * z_q[b, ia, u + mc - MLO]
// grid (4, 8 = ia_q*2 + oa_half, 16) = 512 blocks; block tile 64 oa x 128 u; K = 32 ia * KC
// ia chunked IAC per barrier; taps in groups of 4; z windows via aligned float4 LDS.
template<int KC, int S, int MLO, int IAC>
__global__ __launch_bounds__(256) void conv_collapsed_kernel() {
    const float* gW = wc_ptr<S>();
    constexpr int GF  = KC / 4;                       // full 4-tap groups
    constexpr int ZN4 = ((128 + KC + 11 + 3) / 4) * 4;
    __shared__ float Wsm[IAC][KC][64];
    __shared__ float zsm[IAC][ZN4];
    const int LQ = LLEN / S;
    int r = blockIdx.x % S;
    int u0 = (blockIdx.x / S) * 128;
    int oa_half = blockIdx.y & 1, ia_q = blockIdx.y >> 1;
    int b = blockIdx.z;
    int tid = threadIdx.x;
    int tx = tid & 15, ty = tid >> 4;        // oa = oa_half*64 + tx*4, u = u0 + ty*8 + n
    float acc[4][8];
    #pragma unroll
    for (int m = 0; m < 4; m++)
        #pragma unroll
        for (int n = 0; n < 8; n++) acc[m][n] = 0.f;

    const float* zbase = g_zq + ((size_t)b*NA + ia_q*32) * LLEN;
    const float* wbase = gW + ((size_t)r*128 + ia_q*32) * KC * 128 + oa_half*64;

    for (int i0 = 0; i0 < 32; i0 += IAC) {
        __syncthreads();
        // weights: IAC ia x KC x 16 float4 (oa-contiguous)
        for (int i = tid; i < IAC*KC*16; i += 256) {
            int c = i / (KC*16), rem = i % (KC*16), mc = rem >> 4, q = rem & 15;
            *(float4*)&Wsm[c][mc][q*4] =
                *(const float4*)&wbase[((size_t)(i0 + c)*KC + mc)*128 + q*4];
        }
        // z: IAC x ZN4
        for (int j = tid; j < IAC*ZN4; j += 256) {
            int c = j / ZN4, jj = j % ZN4;
            int uq = u0 - MLO + jj;
            zsm[c][jj] = (uq >= 0 && uq < LQ) ? zbase[(size_t)(i0 + c)*LLEN + uq] : 0.f;
        }
        __syncthreads();
        #pragma unroll 1
        for (int c = 0; c < IAC; c++) {
            #pragma unroll
            for (int g = 0; g < GF; g++) {
                float4 za = *(const float4*)&zsm[c][ty*8 + g*4];
                float4 zb = *(const float4*)&zsm[c][ty*8 + g*4 + 4];
                float4 zc = *(const float4*)&zsm[c][ty*8 + g*4 + 8];
                float zw[12] = {za.x, za.y, za.z, za.w,
                                zb.x, zb.y, zb.z, zb.w,
                                zc.x, zc.y, zc.z, zc.w};
                #pragma unroll
                for (int m = 0; m < 4; m++) {
                    float4 wv = *(const float4*)&Wsm[c][g*4 + m][tx*4];
                    #pragma unroll
                    for (int n = 0; n < 8; n++) {
                        float z = zw[m + n];
                        acc[0][n] += wv.x * z; acc[1][n] += wv.y * z;
                        acc[2][n] += wv.z * z; acc[3][n] += wv.w * z;
                    }
                }
            }
            if constexpr ((KC % 4) != 0) {
                // tail taps (KC%4 = 1 for KC=17,33)
                #pragma unroll
                for (int m = GF*4; m < KC; m++) {
                    float4 za = *(const float4*)&zsm[c][ty*8 + m];
                    float4 zb = *(const float4*)&zsm[c][ty*8 + m + 4];
                    float zw[8] = {za.x, za.y, za.z, za.w, zb.x, zb.y, zb.z, zb.w};
                    float4 wv = *(const float4*)&Wsm[c][m][tx*4];
                    #pragma unroll
                    for (int n = 0; n < 8; n++) {
                        float z = zw[n];
                        acc[0][n] += wv.x * z; acc[1][n] += wv.y * z;
                        acc[2][n] += wv.z * z; acc[3][n] += wv.w * z;
                    }
                }
            }
        }
    }
    int oa = oa_half*64 + tx*4;
    #pragma unroll
    for (int m = 0; m < 4; m++) {
        float* dst = g_rectotal + ((size_t)b*NA + oa + m)*LLEN + r;
        #pragma unroll
        for (int n = 0; n < 8; n++)
            atomicAdd(&dst[(size_t)S*(u0 + ty*8 + n)], acc[m][n]);
    }
}

// ================= decoder =================
__global__ __launch_bounds__(256) void decoder_kernel(const float* __restrict__ dec_b,
                                                      float* __restrict__ out) {
    __shared__ float Wsm[4][3][64];
    __shared__ float zsm[4][130];
    int q0 = blockIdx.x * 128;
    int row0 = blockIdx.y * 64;
    int b = blockIdx.z;
    int tid = threadIdx.x, tx = tid & 15, ty = tid >> 4;
    float acc[4][8];
    #pragma unroll
    for (int m = 0; m < 4; m++)
        #pragma unroll
        for (int n = 0; n < 8; n++) acc[m][n] = 0.f;

    for (int na0 = 0; na0 < NA; na0 += 4) {
        __syncthreads();
        for (int i = tid; i < 768; i += 256) {
            int nl = i / 192, rem = i % 192, m = rem / 64, rl = rem % 64;
            Wsm[nl][m][rl] = g_WdT[((size_t)(na0+nl)*3 + m)*384 + row0 + rl];
        }
        for (int i = tid; i < 520; i += 256) {
            int nl = i / 130, j = i % 130;
            int q = q0 - 1 + j;
            zsm[nl][j] = (q >= 0 && q < LLEN) ? g_rectotal[((size_t)b*NA + na0 + nl)*LLEN + q] : 0.f;
        }
        __syncthreads();
        #pragma unroll
        for (int nl = 0; nl < 4; nl++) {
            float z[10];
            #pragma unroll
            for (int j = 0; j < 10; j++) z[j] = zsm[nl][ty*8 + j];
            #pragma unroll
            for (int m = 0; m < 3; m++) {
                float4 wv = *(const float4*)&Wsm[nl][m][tx*4];
                #pragma unroll
                for (int n = 0; n < 8; n++) {
                    float zz = z[n + m];
                    acc[0][n] += wv.x * zz; acc[1][n] += wv.y * zz;
                    acc[2][n] += wv.z * zz; acc[3][n] += wv.w * zz;
                }
            }
        }
    }
    int row = row0 + tx*4;
    int c = row >> 5, r0 = row & 31;
    float sd = g_std[b*CIN + c], mn = g_mean[b*CIN + c], bb = dec_b[c];
    float* ob = out + ((size_t)(b*CIN + c)) * TLEN;
    #pragma unroll
    for (int n = 0; n < 8; n++) {
        int q = q0 + ty*8 + n;
        if (q < 511) {
            float4 v;
            v.x = (acc[0][n] + bb) * sd + mn;
            v.y = (acc[1][n] + bb) * sd + mn;
            v.z = (acc[2][n] + bb) * sd + mn;
            v.w = (acc[3][n] + bb) * sd + mn;
            *(float4*)&ob[q*32 + r0] = v;
        }
    }
}

__global__ void finalize_kernel(float* __restrict__ out) {
    out[NOUT]     = 0.f;
    out[NOUT + 1] = 0.01f * (g_l1[0] / (16.f*128.f*128.f)
                           + g_l1[1] / (16.f*128.f*256.f)
                           + g_l1[2] / (16.f*128.f*512.f));
}

// ================= launch =================
extern "C" void kernel_launch(void* const* d_in, const int* in_sizes, int n_in,
                              void* d_out, int out_size) {
    const float* x   = (const float*)d_in[0];
    const float* w1  = (const float*)d_in[1];
    const float* b1  = (const float*)d_in[2];
    const float* w2  = (const float*)d_in[3];
    const float* b2  = (const float*)d_in[4];
    const float* scl = (const float*)d_in[5];
    const float* shp = (const float*)d_in[6];
    const float* dw  = (const float*)d_in[7];
    const float* db  = (const float*)d_in[8];
    float* out = (float*)d_out;

    fused_prep_kernel<<<NROWS + 32, 256>>>(x, w1, w2, shp, dw);         // 1
    fused_stem_kernel<<<1024, 256>>>(b1);                               // 2
    conv1x1_pool4_kernel<<<dim3(8, BATCH), 256>>>(b2, scl);             // 3
    conv_collapsed_kernel<17, 4, 8,  4><<<dim3(4, 8, BATCH), 256>>>();  // 4 (profiled)
    pool_kernel<<<BATCH*NA, 128>>>(2, 1);                               // 5
    conv_collapsed_kernel<33, 2, 16, 4><<<dim3(4, 8, BATCH), 256>>>();  // 6
    pool_kernel<<<BATCH*NA, 128>>>(1, 2);                               // 7
    conv_collapsed_kernel<64, 1, 31, 2><<<dim3(4, 8, BATCH), 256>>>();  // 8
    decoder_kernel<<<dim3(4, 6, BATCH), 256>>>(db, out);                // 9
    if (out_size >= NOUT + 2) finalize_kernel<<<1, 1>>>(out);           // 10
}

// round 11
// speedup vs baseline: 1.5363x; 1.0366x over previous
#include <cuda_runtime.h>
#include <math.h>
#include <stdint.h>

// ---------------- problem constants ----------------
#define BATCH   16
#define CIN     12
#define TLEN    16352
#define ATOM    64
#define STRIDE  32
#define NA      128
#define LLEN    512
#define NROWS   (BATCH*CIN)
#define NOUT    (BATCH*CIN*TLEN)

// ---------------- scratch (device globals) ----------------
__device__ float g_mean[NROWS];
__device__ float g_std[NROWS];
__device__ float g_xnorm[(size_t)BATCH*CIN*TLEN];
__device__ float g_h[(size_t)BATCH*LLEN*64];
__device__ float g_zraw[(size_t)BATCH*NA*LLEN];
__device__ float g_zq[(size_t)BATCH*NA*LLEN];          // compact z_q, row stride 512
__device__ float g_rectotal[(size_t)BATCH*NA*LLEN];
__device__ float g_w1t[12*64*64];
__device__ float g_w2t[64*128];
__device__ float g_shpnT[(size_t)NA*ATOM*NA];          // [(ia*64+k)*128 + oa]  (== Wc for s=1)
__device__ float g_Wc4[(size_t)4*128*17*128];          // [((r*128+ia)*17+mc)*128+oa]
__device__ float g_Wc2[(size_t)2*128*33*128];
__device__ float g_WdT[(size_t)NA*3*384];
__device__ float g_l1[3];

template<int SEL> __device__ __forceinline__ const float* wc_ptr();
template<> __device__ __forceinline__ const float* wc_ptr<4>() { return g_Wc4; }
template<> __device__ __forceinline__ const float* wc_ptr<2>() { return g_Wc2; }
template<> __device__ __forceinline__ const float* wc_ptr<1>() { return g_shpnT; }

// ================= L1: fused stats+norm + misc preps + rectotal zero =================
__global__ __launch_bounds__(256) void fused_prep_kernel(
    const float* __restrict__ x,  const float* __restrict__ w1,
    const float* __restrict__ w2, const float* __restrict__ shp,
    const float* __restrict__ dw)
{
    int bid = blockIdx.x, tid = threadIdx.x;
    if (bid < NROWS) {
        int row = bid;
        const float* p = x + (size_t)row * TLEN;
        float s = 0.f, s2 = 0.f;
        for (int i = tid; i < TLEN; i += 256) { float v = p[i]; s += v; s2 += v*v; }
        __shared__ float sh[256], sh2[256];
        sh[tid] = s; sh2[tid] = s2;
        __syncthreads();
        for (int st = 128; st > 0; st >>= 1) {
            if (tid < st) { sh[tid] += sh[tid+st]; sh2[tid] += sh2[tid+st]; }
            __syncthreads();
        }
        __shared__ float smean, sistd;
        if (tid == 0) {
            float mean = sh[0] / (float)TLEN;
            float var  = sh2[0] / (float)TLEN - mean * mean;
            float sd   = sqrtf(var + 1e-5f);
            g_mean[row] = mean; g_std[row] = sd;
            smean = mean; sistd = 1.f / sd;
        }
        __syncthreads();
        float mean = smean, istd = sistd;
        size_t base = (size_t)row * TLEN;
        for (int i = tid; i < TLEN; i += 256)
            g_xnorm[base + i] = (p[i] - mean) * istd;
    } else {
        int base = (bid - NROWS) * 256 + tid;   // 0..8191
        // zero rec_total (conv kernels accumulate with atomics)
        {
            float4 z4 = make_float4(0.f, 0.f, 0.f, 0.f);
            float4* rt4 = (float4*)g_rectotal;
            for (int i = base; i < (BATCH*NA*LLEN)/4; i += 8192) rt4[i] = z4;
        }
        for (int i = base; i < 64*768; i += 8192) {
            int o = i / 768, ck = i % 768;
            g_w1t[ck*64 + o] = w1[i];
        }
        for (int i = base; i < 128*64; i += 8192) {
            int a = i >> 6, o = i & 63;
            g_w2t[o*128 + a] = w2[i];
        }
        for (int i = base; i < 384*NA*3; i += 8192) {
            int row = i % 384; int rest = i / 384; int m = rest % 3; int na = rest / 3;
            int c = row >> 5, r = row & 31;
            int d = m - 1;
            int klo = 32*d + 31 - r; if (klo < 0) klo = 0;
            int khi = 32*d + 62 - r; if (khi > 63) khi = 63;
            float s = 0.f;
            const float* p = dw + ((size_t)c*NA + na) * ATOM;
            for (int k = klo; k <= khi; k++) s += p[k];
            g_WdT[((size_t)na*3 + m)*384 + row] = s;
        }
        for (int i = base; i < NA*NA; i += 8192) {
            int oa = i >> 7, ia = i & 127;
            const float* p = shp + ((size_t)oa*NA + ia) * ATOM;
            float s = 0.f;
            for (int k = 0; k < ATOM; k++) { float v = p[k]; s += v*v; }
            float inv = 1.f / fmaxf(sqrtf(s), 1e-8f);
            for (int k = 0; k < ATOM; k++)
                g_shpnT[((size_t)ia*ATOM + k)*NA + oa] = p[k] * inv;
        }
        if (base < 3) g_l1[base] = 0.f;
    }
}

// ================= L2: fused stem + collapsed-weight prep =================
__device__ __forceinline__ void wc_compute(float* gW, int S, int KC, int MLO, int i) {
    int oa = i & 127;
    int rest = i >> 7;
    int mc = rest % KC;
    int rest2 = rest / KC;
    int ia = rest2 & 127;
    int r  = rest2 >> 7;
    int m = mc - MLO;
    int klo = S*m + 31 - r;
    int khi = klo + S - 1;
    if (klo < 0) klo = 0;
    if (khi > 63) khi = 63;
    float s = 0.f;
    for (int k = klo; k <= khi; k++)
        s += g_shpnT[((size_t)ia*ATOM + k)*NA + oa];
    gW[i] = s;
}

__global__ __launch_bounds__(256) void fused_stem_kernel(const float* __restrict__ b1) {
    __shared__ float xw[12][576];
    int bid = blockIdx.x, tid = threadIdx.x;
    if (bid < 512) {
        int b = bid >> 5, l0 = (bid & 31) * 16;
        for (int j = tid; j < 12*576; j += 256) {
            int c = j / 576, jj = j % 576;
            int g = 32*l0 - 32 + jj;
            xw[c][jj] = (g >= 0 && g < TLEN) ? g_xnorm[((size_t)b*CIN + c)*TLEN + g] : 0.f;
        }
        __syncthreads();
        int o = tid & 63, lh = tid >> 6;   // lh 0..3, 4 l each
        float acc[4] = {0,0,0,0};
        for (int c = 0; c < 12; c++) {
            #pragma unroll 4
            for (int k = 0; k < 64; k++) {
                float w = g_w1t[(c*64 + k)*64 + o];
                #pragma unroll
                for (int i = 0; i < 4; i++)
                    acc[i] += w * xw[c][32*(lh*4 + i) + k];
            }
        }
        float bo = b1[o];
        #pragma unroll
        for (int i = 0; i < 4; i++) {
            int l = l0 + lh*4 + i;
            g_h[((size_t)b*LLEN + l)*64 + o] = fmaxf(acc[i] + bo, 0.f);
        }
    } else {
        int base = (bid - 512) * 256 + tid;      // 0..131071
        const int N4 = 4*128*17*128;
        const int N2 = 2*128*33*128;
        for (int i = base; i < N4; i += 512*256) wc_compute(g_Wc4, 4, 17, 8,  i);
        for (int i = base; i < N2; i += 512*256) wc_compute(g_Wc2, 2, 33, 16, i);
    }
}

// ================= L3: 1x1 conv + fused s=4 pool + l1[0] =================
__global__ __launch_bounds__(256) void conv1x1_pool4_kernel(const float* __restrict__ b2,
                                                            const float* __restrict__ scale) {
    __shared__ float hsm[64][64];     // reused as reduction buffer at the end
    __shared__ float w2sm[64][128];
    int l0 = blockIdx.x * 64, b = blockIdx.y;
    int tid = threadIdx.x;
    for (int i = tid; i < 4096; i += 256) hsm[i >> 6][i & 63] = g_h[((size_t)b*LLEN + l0)*64 + i];
    for (int i = tid; i < 8192; i += 256) w2sm[i >> 7][i & 127] = g_w2t[i];
    __syncthreads();
    int tx = tid & 31, ty = tid >> 5;
    float acc[4][8];
    #pragma unroll
    for (int m = 0; m < 4; m++)
        #pragma unroll
        for (int n = 0; n < 8; n++) acc[m][n] = 0.f;
    for (int o = 0; o < 64; o++) {
        float4 wv = *(const float4*)&w2sm[o][tx*4];
        #pragma unroll
        for (int n = 0; n < 8; n++) {
            float hv = hsm[ty*8 + n][o];
            acc[0][n] += wv.x * hv; acc[1][n] += wv.y * hv;
            acc[2][n] += wv.z * hv; acc[3][n] += wv.w * hv;
        }
    }
    float sc = scale[0];
    float l1loc = 0.f;
    #pragma unroll
    for (int m = 0; m < 4; m++) {
        int a = tx*4 + m;
        float bb = b2[a];
        size_t rowb = ((size_t)b*NA + a)*LLEN;
        #pragma unroll
        for (int n = 0; n < 8; n++) {
            float v = (acc[m][n] + bb) * sc;
            acc[m][n] = v;
            g_zraw[rowb + l0 + ty*8 + n] = v;
        }
        #pragma unroll
        for (int h = 0; h < 2; h++) {
            float zq = 0.25f * (acc[m][4*h] + acc[m][4*h+1] + acc[m][4*h+2] + acc[m][4*h+3]);
            g_zq[rowb + l0/4 + 2*ty + h] = zq;
            l1loc += fabsf(zq);
        }
    }
    __syncthreads();
    float* red = &hsm[0][0];
    red[tid] = l1loc;
    __syncthreads();
    for (int st = 128; st > 0; st >>= 1) {
        if (tid < st) red[tid] += red[tid + st];
        __syncthreads();
    }
    if (tid == 0) atomicAdd(&g_l1[0], red[0]);
}

// ================= pool (scales 2, 1): residual -> compact z_q + l1 =================
__global__ __launch_bounds__(128) void pool_kernel(int s, int idx) {
    int row = blockIdx.x;                 // b*128 + a
    size_t base = (size_t)row * LLEN;
    int nq = LLEN / s;
    float inv = 1.f / (float)s;
    float local = 0.f;
    for (int j = threadIdx.x; j < nq; j += 128) {
        int t0 = j * s;
        float sum = 0.f;
        for (int t = 0; t < s; t++) sum += g_zraw[base + t0 + t] - g_rectotal[base + t0 + t];
        float zq = sum * inv;
        local += fabsf(zq);
        g_zq[base + j] = zq;
    }
    __shared__ float red[128];
    red[threadIdx.x] = local;
    __syncthreads();
    for (int st = 64; st > 0; st >>= 1) {
        if (threadIdx.x < st) red[threadIdx.x] += red[threadIdx.x + st];
        __syncthreads();
    }
    if (threadIdx.x == 0) atomicAdd(&g_l1[idx], red[0]);
}

// ================= collapsed shapelet conv =================
// rec_total[b, oa, S*u + r] += sum_{ia, mc} Wc[r][ia][mc][oa] * z_q[b, ia, u + mc - MLO]
// grid (4, 16 = ia_q*2 + oa_half, 16) = 1024 blocks; block tile 64 oa x 128 u; K = 16 ia * KC
// ia chunked IAC per barrier; taps in groups of 4; z windows via aligned float4 LDS.
template<int KC, int S, int MLO, int IAC>
__global__ __launch_bounds__(256) void conv_collapsed_kernel() {
    const float* gW = wc_ptr<S>();
    constexpr int GF  = KC / 4;                       // full 4-tap groups
    constexpr int ZN4 = ((128 + KC + 11 + 3) / 4) * 4;
    __shared__ float Wsm[IAC][KC][64];
    __shared__ float zsm[IAC][ZN4];
    const int LQ = LLEN / S;
    int r = blockIdx.x % S;
    int u0 = (blockIdx.x / S) * 128;
    int oa_half = blockIdx.y & 1, ia_q = blockIdx.y >> 1;   // ia_q 0..7
    int b = blockIdx.z;
    int tid = threadIdx.x;
    int tx = tid & 15, ty = tid >> 4;        // oa = oa_half*64 + tx*4, u = u0 + ty*8 + n
    float acc[4][8];
    #pragma unroll
    for (int m = 0; m < 4; m++)
        #pragma unroll
        for (int n = 0; n < 8; n++) acc[m][n] = 0.f;

    const float* zbase = g_zq + ((size_t)b*NA + ia_q*16) * LLEN;
    const float* wbase = gW + ((size_t)r*128 + ia_q*16) * KC * 128 + oa_half*64;

    for (int i0 = 0; i0 < 16; i0 += IAC) {
        __syncthreads();
        // weights: IAC ia x KC x 16 float4 (oa-contiguous)
        for (int i = tid; i < IAC*KC*16; i += 256) {
            int c = i / (KC*16), rem = i % (KC*16), mc = rem >> 4, q = rem & 15;
            *(float4*)&Wsm[c][mc][q*4] =
                *(const float4*)&wbase[((size_t)(i0 + c)*KC + mc)*128 + q*4];
        }
        // z: IAC x ZN4
        for (int j = tid; j < IAC*ZN4; j += 256) {
            int c = j / ZN4, jj = j % ZN4;
            int uq = u0 - MLO + jj;
            zsm[c][jj] = (uq >= 0 && uq < LQ) ? zbase[(size_t)(i0 + c)*LLEN + uq] : 0.f;
        }
        __syncthreads();
        #pragma unroll 1
        for (int c = 0; c < IAC; c++) {
            #pragma unroll
            for (int g = 0; g < GF; g++) {
                float4 za = *(const float4*)&zsm[c][ty*8 + g*4];
                float4 zb = *(const float4*)&zsm[c][ty*8 + g*4 + 4];
                float4 zc = *(const float4*)&zsm[c][ty*8 + g*4 + 8];
                float zw[12] = {za.x, za.y, za.z, za.w,
                                zb.x, zb.y, zb.z, zb.w,
                                zc.x, zc.y, zc.z, zc.w};
                #pragma unroll
                for (int m = 0; m < 4; m++) {
                    float4 wv = *(const float4*)&Wsm[c][g*4 + m][tx*4];
                    #pragma unroll
                    for (int n = 0; n < 8; n++) {
                        float z = zw[m + n];
                        acc[0][n] += wv.x * z; acc[1][n] += wv.y * z;
                        acc[2][n] += wv.z * z; acc[3][n] += wv.w * z;
                    }
                }
            }
            if constexpr ((KC % 4) != 0) {
                // tail taps (KC%4 = 1 for KC=17,33)
                #pragma unroll
                for (int m = GF*4; m < KC; m++) {
                    float4 za = *(const float4*)&zsm[c][ty*8 + m];
                    float4 zb = *(const float4*)&zsm[c][ty*8 + m + 4];
                    float zw[8] = {za.x, za.y, za.z, za.w, zb.x, zb.y, zb.z, zb.w};
                    float4 wv = *(const float4*)&Wsm[c][m][tx*4];
                    #pragma unroll
                    for (int n = 0; n < 8; n++) {
                        float z = zw[n];
                        acc[0][n] += wv.x * z; acc[1][n] += wv.y * z;
                        acc[2][n] += wv.z * z; acc[3][n] += wv.w * z;
                    }
                }
            }
        }
    }
    int oa = oa_half*64 + tx*4;
    #pragma unroll
    for (int m = 0; m < 4; m++) {
        float* dst = g_rectotal + ((size_t)b*NA + oa + m)*LLEN + r;
        #pragma unroll
        for (int n = 0; n < 8; n++)
            atomicAdd(&dst[(size_t)S*(u0 + ty*8 + n)], acc[m][n]);
    }
}

// ================= decoder =================
__global__ __launch_bounds__(256) void decoder_kernel(const float* __restrict__ dec_b,
                                                      float* __restrict__ out) {
    __shared__ float Wsm[4][3][64];
    __shared__ float zsm[4][130];
    int q0 = blockIdx.x * 128;
    int row0 = blockIdx.y * 64;
    int b = blockIdx.z;
    int tid = threadIdx.x, tx = tid & 15, ty = tid >> 4;
    float acc[4][8];
    #pragma unroll
    for (int m = 0; m < 4; m++)
        #pragma unroll
        for (int n = 0; n < 8; n++) acc[m][n] = 0.f;

    for (int na0 = 0; na0 < NA; na0 += 4) {
        __syncthreads();
        for (int i = tid; i < 768; i += 256) {
            int nl = i / 192, rem = i % 192, m = rem / 64, rl = rem % 64;
            Wsm[nl][m][rl] = g_WdT[((size_t)(na0+nl)*3 + m)*384 + row0 + rl];
        }
        for (int i = tid; i < 520; i += 256) {
            int nl = i / 130, j = i % 130;
            int q = q0 - 1 + j;
            zsm[nl][j] = (q >= 0 && q < LLEN) ? g_rectotal[((size_t)b*NA + na0 + nl)*LLEN + q] : 0.f;
        }
        __syncthreads();
        #pragma unroll
        for (int nl = 0; nl < 4; nl++) {
            float z[10];
            #pragma unroll
            for (int j = 0; j < 10; j++) z[j] = zsm[nl][ty*8 + j];
            #pragma unroll
            for (int m = 0; m < 3; m++) {
                float4 wv = *(const float4*)&Wsm[nl][m][tx*4];
                #pragma unroll
                for (int n = 0; n < 8; n++) {
                    float zz = z[n + m];
                    acc[0][n] += wv.x * zz; acc[1][n] += wv.y * zz;
                    acc[2][n] += wv.z * zz; acc[3][n] += wv.w * zz;
                }
            }
        }
    }
    int row = row0 + tx*4;
    int c = row >> 5, r0 = row & 31;
    float sd = g_std[b*CIN + c], mn = g_mean[b*CIN + c], bb = dec_b[c];
    float* ob = out + ((size_t)(b*CIN + c)) * TLEN;
    #pragma unroll
    for (int n = 0; n < 8; n++) {
        int q = q0 + ty*8 + n;
        if (q < 511) {
            float4 v;
            v.x = (acc[0][n] + bb) * sd + mn;
            v.y = (acc[1][n] + bb) * sd + mn;
            v.z = (acc[2][n] + bb) * sd + mn;
            v.w = (acc[3][n] + bb) * sd + mn;
            *(float4*)&ob[q*32 + r0] = v;
        }
    }
}

__global__ void finalize_kernel(float* __restrict__ out) {
    out[NOUT]     = 0.f;
    out[NOUT + 1] = 0.01f * (g_l1[0] / (16.f*128.f*128.f)
                           + g_l1[1] / (16.f*128.f*256.f)
                           + g_l1[2] / (16.f*128.f*512.f));
}

// ================= launch =================
extern "C" void kernel_launch(void* const* d_in, const int* in_sizes, int n_in,
                              void* d_out, int out_size) {
    const float* x   = (const float*)d_in[0];
    const float* w1  = (const float*)d_in[1];
    const float* b1  = (const float*)d_in[2];
    const float* w2  = (const float*)d_in[3];
    const float* b2  = (const float*)d_in[4];
    const float* scl = (const float*)d_in[5];
    const float* shp = (const float*)d_in[6];
    const float* dw  = (const float*)d_in[7];
    const float* db  = (const float*)d_in[8];
    float* out = (float*)d_out;

    fused_prep_kernel<<<NROWS + 32, 256>>>(x, w1, w2, shp, dw);          // 1
    fused_stem_kernel<<<1024, 256>>>(b1);                                // 2
    conv1x1_pool4_kernel<<<dim3(8, BATCH), 256>>>(b2, scl);              // 3
    conv_collapsed_kernel<17, 4, 8,  4><<<dim3(4, 16, BATCH), 256>>>();  // 4 (profiled)
    pool_kernel<<<BATCH*NA, 128>>>(2, 1);                                // 5
    conv_collapsed_kernel<33, 2, 16, 4><<<dim3(4, 16, BATCH), 256>>>();  // 6
    pool_kernel<<<BATCH*NA, 128>>>(1, 2);                                // 7
    conv_collapsed_kernel<64, 1, 31, 2><<<dim3(4, 16, BATCH), 256>>>();  // 8
    decoder_kernel<<<dim3(4, 6, BATCH), 256>>>(db, out);                 // 9
    if (out_size >= NOUT + 2) finalize_kernel<<<1, 1>>>(out);            // 10
}

// round 13
// speedup vs baseline: 2.2469x; 1.4625x over previous
#include <cuda_runtime.h>
#include <cuda_bf16.h>
#include <math.h>
#include <stdint.h>

// ---------------- problem constants ----------------
#define BATCH   16
#define CIN     12
#define TLEN    16352
#define ATOM    64
#define STRIDE  32
#define NA      128
#define LLEN    512
#define NROWS   (BATCH*CIN)
#define NOUT    (BATCH*CIN*TLEN)

// ---------------- scratch (device globals) ----------------
__device__ float g_mean[NROWS];
__device__ float g_std[NROWS];
__device__ float g_xnorm[(size_t)BATCH*CIN*TLEN];
__device__ float g_h[(size_t)BATCH*LLEN*64];
__device__ float g_zraw[(size_t)BATCH*NA*LLEN];
__device__ float g_zq[(size_t)BATCH*NA*LLEN];          // compact z_q, row stride 512
__device__ float g_rectotal[(size_t)BATCH*NA*LLEN];
__device__ float g_w1t[12*64*64];
__device__ float g_w2t[64*128];
__device__ float g_shpnT[(size_t)NA*ATOM*NA];          // [(ia*64+k)*128 + oa]
__device__ float g_Wc4[(size_t)4*128*17*128];          // [((r*128+ia)*17+mc)*128+oa]
__device__ float g_Wc2[(size_t)2*128*33*128];
__device__ float g_WdT[(size_t)NA*3*384];
__device__ float g_l1[3];
// packed bf16x2 hi/lo weight tiles: [((r*KC+mc)*64 + kp)*128 + oa], pair = (ia=2kp lo16, ia=2kp+1 hi16)
__device__ uint32_t g_WpH4[(size_t)4*17*64*128];
__device__ uint32_t g_WpL4[(size_t)4*17*64*128];
__device__ uint32_t g_WpH2[(size_t)2*33*64*128];
__device__ uint32_t g_WpL2[(size_t)2*33*64*128];
__device__ uint32_t g_WpH1[(size_t)1*64*64*128];
__device__ uint32_t g_WpL1[(size_t)1*64*64*128];

#define MMA_BF16(c, a, b0_, b1_) \
    asm volatile("mma.sync.aligned.m16n8k16.row.col.f32.bf16.bf16.f32 " \
        "{%0,%1,%2,%3}, {%4,%5,%6,%7}, {%8,%9}, {%0,%1,%2,%3};" \
        : "+f"((c)[0]), "+f"((c)[1]), "+f"((c)[2]), "+f"((c)[3]) \
        : "r"((a)[0]), "r"((a)[1]), "r"((a)[2]), "r"((a)[3]), "r"(b0_), "r"(b1_))

__device__ __forceinline__ uint32_t pack_bf16x2(float v0, float v1) {
    __nv_bfloat16 h0 = __float2bfloat16(v0);
    __nv_bfloat16 h1 = __float2bfloat16(v1);
    return ((uint32_t)__bfloat16_as_ushort(h1) << 16) | (uint32_t)__bfloat16_as_ushort(h0);
}
__device__ __forceinline__ void split_pack(float v0, float v1, uint32_t& h, uint32_t& l) {
    __nv_bfloat16 h0 = __float2bfloat16(v0);
    __nv_bfloat16 h1 = __float2bfloat16(v1);
    float l0 = v0 - __bfloat162float(h0);
    float l1 = v1 - __bfloat162float(h1);
    h = ((uint32_t)__bfloat16_as_ushort(h1) << 16) | (uint32_t)__bfloat16_as_ushort(h0);
    l = pack_bf16x2(l0, l1);
}

// ================= L1: fused stats+norm + misc preps + rectotal zero =================
__global__ __launch_bounds__(256) void fused_prep_kernel(
    const float* __restrict__ x,  const float* __restrict__ w1,
    const float* __restrict__ w2, const float* __restrict__ shp,
    const float* __restrict__ dw)
{
    int bid = blockIdx.x, tid = threadIdx.x;
    if (bid < NROWS) {
        int row = bid;
        const float* p = x + (size_t)row * TLEN;
        float s = 0.f, s2 = 0.f;
        for (int i = tid; i < TLEN; i += 256) { float v = p[i]; s += v; s2 += v*v; }
        __shared__ float sh[256], sh2[256];
        sh[tid] = s; sh2[tid] = s2;
        __syncthreads();
        for (int st = 128; st > 0; st >>= 1) {
            if (tid < st) { sh[tid] += sh[tid+st]; sh2[tid] += sh2[tid+st]; }
            __syncthreads();
        }
        __shared__ float smean, sistd;
        if (tid == 0) {
            float mean = sh[0] / (float)TLEN;
            float var  = sh2[0] / (float)TLEN - mean * mean;
            float sd   = sqrtf(var + 1e-5f);
            g_mean[row] = mean; g_std[row] = sd;
            smean = mean; sistd = 1.f / sd;
        }
        __syncthreads();
        float mean = smean, istd = sistd;
        size_t base = (size_t)row * TLEN;
        for (int i = tid; i < TLEN; i += 256)
            g_xnorm[base + i] = (p[i] - mean) * istd;
    } else {
        int base = (bid - NROWS) * 256 + tid;   // 0..8191
        {
            float4 z4 = make_float4(0.f, 0.f, 0.f, 0.f);
            float4* rt4 = (float4*)g_rectotal;
            for (int i = base; i < (BATCH*NA*LLEN)/4; i += 8192) rt4[i] = z4;
        }
        for (int i = base; i < 64*768; i += 8192) {
            int o = i / 768, ck = i % 768;
            g_w1t[ck*64 + o] = w1[i];
        }
        for (int i = base; i < 128*64; i += 8192) {
            int a = i >> 6, o = i & 63;
            g_w2t[o*128 + a] = w2[i];
        }
        for (int i = base; i < 384*NA*3; i += 8192) {
            int row = i % 384; int rest = i / 384; int m = rest % 3; int na = rest / 3;
            int c = row >> 5, r = row & 31;
            int d = m - 1;
            int klo = 32*d + 31 - r; if (klo < 0) klo = 0;
            int khi = 32*d + 62 - r; if (khi > 63) khi = 63;
            float s = 0.f;
            const float* p = dw + ((size_t)c*NA + na) * ATOM;
            for (int k = klo; k <= khi; k++) s += p[k];
            g_WdT[((size_t)na*3 + m)*384 + row] = s;
        }
        for (int i = base; i < NA*NA; i += 8192) {
            int oa = i >> 7, ia = i & 127;
            const float* p = shp + ((size_t)oa*NA + ia) * ATOM;
            float s = 0.f;
            for (int k = 0; k < ATOM; k++) { float v = p[k]; s += v*v; }
            float inv = 1.f / fmaxf(sqrtf(s), 1e-8f);
            for (int k = 0; k < ATOM; k++)
                g_shpnT[((size_t)ia*ATOM + k)*NA + oa] = p[k] * inv;
        }
        if (base < 3) g_l1[base] = 0.f;
    }
}

// ================= L2: fused stem + collapsed-weight prep =================
__device__ __forceinline__ void wc_compute(float* gW, int S, int KC, int MLO, int i) {
    int oa = i & 127;
    int rest = i >> 7;
    int mc = rest % KC;
    int rest2 = rest / KC;
    int ia = rest2 & 127;
    int r  = rest2 >> 7;
    int m = mc - MLO;
    int klo = S*m + 31 - r;
    int khi = klo + S - 1;
    if (klo < 0) klo = 0;
    if (khi > 63) khi = 63;
    float s = 0.f;
    for (int k = klo; k <= khi; k++)
        s += g_shpnT[((size_t)ia*ATOM + k)*NA + oa];
    gW[i] = s;
}

__global__ __launch_bounds__(256) void fused_stem_kernel(const float* __restrict__ b1) {
    __shared__ float xw[12][576];
    int bid = blockIdx.x, tid = threadIdx.x;
    if (bid < 512) {
        int b = bid >> 5, l0 = (bid & 31) * 16;
        for (int j = tid; j < 12*576; j += 256) {
            int c = j / 576, jj = j % 576;
            int g = 32*l0 - 32 + jj;
            xw[c][jj] = (g >= 0 && g < TLEN) ? g_xnorm[((size_t)b*CIN + c)*TLEN + g] : 0.f;
        }
        __syncthreads();
        int o = tid & 63, lh = tid >> 6;
        float acc[4] = {0,0,0,0};
        for (int c = 0; c < 12; c++) {
            #pragma unroll 4
            for (int k = 0; k < 64; k++) {
                float w = g_w1t[(c*64 + k)*64 + o];
                #pragma unroll
                for (int i = 0; i < 4; i++)
                    acc[i] += w * xw[c][32*(lh*4 + i) + k];
            }
        }
        float bo = b1[o];
        #pragma unroll
        for (int i = 0; i < 4; i++) {
            int l = l0 + lh*4 + i;
            g_h[((size_t)b*LLEN + l)*64 + o] = fmaxf(acc[i] + bo, 0.f);
        }
    } else {
        int base = (bid - 512) * 256 + tid;      // 0..131071
        const int N4 = 4*128*17*128;
        const int N2 = 2*128*33*128;
        for (int i = base; i < N4; i += 512*256) wc_compute(g_Wc4, 4, 17, 8,  i);
        for (int i = base; i < N2; i += 512*256) wc_compute(g_Wc2, 2, 33, 16, i);
    }
}

// ================= L3: 1x1 conv + fused s=4 pool + l1[0] + bf16 weight pack =================
__global__ __launch_bounds__(256) void conv1x1_pool4_pack_kernel(const float* __restrict__ b2,
                                                                 const float* __restrict__ scale) {
    __shared__ float hsm[64][64];
    __shared__ float w2sm[64][128];
    int bx = blockIdx.x, b = blockIdx.y;
    int tid = threadIdx.x;
    if (bx >= 8) {
        // ---- weight packing blocks: 256 blocks total, grid-stride ----
        const int PN4 = 4*17*64*128;     // 557056
        const int PN2 = 2*33*64*128;     // 540672
        const int PN1 = 64*64*128;       // 524288
        int gtid = ((bx - 8) + b * 16) * 256 + tid;
        for (int idx = gtid; idx < PN4 + PN2 + PN1; idx += 256*256) {
            int seg, li;
            if (idx < PN4) { seg = 0; li = idx; }
            else if (idx < PN4 + PN2) { seg = 1; li = idx - PN4; }
            else { seg = 2; li = idx - PN4 - PN2; }
            int KC = (seg == 0) ? 17 : (seg == 1 ? 33 : 64);
            int oa = li & 127;
            int t  = li >> 7;
            int kp = t & 63;
            int t2 = t >> 6;
            int mc = t2 % KC;
            int r  = t2 / KC;
            int ia0 = kp * 2;
            float v0, v1;
            if (seg == 0) {
                v0 = g_Wc4[(((size_t)r*128 + ia0    )*17 + mc)*128 + oa];
                v1 = g_Wc4[(((size_t)r*128 + ia0 + 1)*17 + mc)*128 + oa];
            } else if (seg == 1) {
                v0 = g_Wc2[(((size_t)r*128 + ia0    )*33 + mc)*128 + oa];
                v1 = g_Wc2[(((size_t)r*128 + ia0 + 1)*33 + mc)*128 + oa];
            } else {
                v0 = g_shpnT[((size_t)(ia0    )*64 + mc)*128 + oa];
                v1 = g_shpnT[((size_t)(ia0 + 1)*64 + mc)*128 + oa];
            }
            uint32_t h, l;
            split_pack(v0, v1, h, l);
            if (seg == 0)      { g_WpH4[li] = h; g_WpL4[li] = l; }
            else if (seg == 1) { g_WpH2[li] = h; g_WpL2[li] = l; }
            else               { g_WpH1[li] = h; g_WpL1[li] = l; }
        }
        return;
    }
    // ---- conv1x1 + pool4 ----
    int l0 = bx * 64;
    for (int i = tid; i < 4096; i += 256) hsm[i >> 6][i & 63] = g_h[((size_t)b*LLEN + l0)*64 + i];
    for (int i = tid; i < 8192; i += 256) w2sm[i >> 7][i & 127] = g_w2t[i];
    __syncthreads();
    int tx = tid & 31, ty = tid >> 5;
    float acc[4][8];
    #pragma unroll
    for (int m = 0; m < 4; m++)
        #pragma unroll
        for (int n = 0; n < 8; n++) acc[m][n] = 0.f;
    for (int o = 0; o < 64; o++) {
        float4 wv = *(const float4*)&w2sm[o][tx*4];
        #pragma unroll
        for (int n = 0; n < 8; n++) {
            float hv = hsm[ty*8 + n][o];
            acc[0][n] += wv.x * hv; acc[1][n] += wv.y * hv;
            acc[2][n] += wv.z * hv; acc[3][n] += wv.w * hv;
        }
    }
    float sc = scale[0];
    float l1loc = 0.f;
    #pragma unroll
    for (int m = 0; m < 4; m++) {
        int a = tx*4 + m;
        float bb = b2[a];
        size_t rowb = ((size_t)b*NA + a)*LLEN;
        #pragma unroll
        for (int n = 0; n < 8; n++) {
            float v = (acc[m][n] + bb) * sc;
            acc[m][n] = v;
            g_zraw[rowb + l0 + ty*8 + n] = v;
        }
        #pragma unroll
        for (int h = 0; h < 2; h++) {
            float zq = 0.25f * (acc[m][4*h] + acc[m][4*h+1] + acc[m][4*h+2] + acc[m][4*h+3]);
            g_zq[rowb + l0/4 + 2*ty + h] = zq;
            l1loc += fabsf(zq);
        }
    }
    __syncthreads();
    float* red = &hsm[0][0];
    red[tid] = l1loc;
    __syncthreads();
    for (int st = 128; st > 0; st >>= 1) {
        if (tid < st) red[tid] += red[tid + st];
        __syncthreads();
    }
    if (tid == 0) atomicAdd(&g_l1[0], red[0]);
}

// ================= pool (scales 2, 1) =================
__global__ __launch_bounds__(128) void pool_kernel(int s, int idx) {
    int row = blockIdx.x;
    size_t base = (size_t)row * LLEN;
    int nq = LLEN / s;
    float inv = 1.f / (float)s;
    float local = 0.f;
    for (int j = threadIdx.x; j < nq; j += 128) {
        int t0 = j * s;
        float sum = 0.f;
        for (int t = 0; t < s; t++) sum += g_zraw[base + t0 + t] - g_rectotal[base + t0 + t];
        float zq = sum * inv;
        local += fabsf(zq);
        g_zq[base + j] = zq;
    }
    __shared__ float red[128];
    red[threadIdx.x] = local;
    __syncthreads();
    for (int st = 64; st > 0; st >>= 1) {
        if (threadIdx.x < st) red[threadIdx.x] += red[threadIdx.x + st];
        __syncthreads();
    }
    if (threadIdx.x == 0) atomicAdd(&g_l1[idx], red[0]);
}

// ================= tensor-core collapsed conv (mma.sync bf16 hi/lo split) =================
// D[oa, S*u+r] += sum_{ia,mc} Wc[r][ia][mc][oa] * zq[ia][u+mc-MLO]
// grid (4 = (LQ/128)*S, 8 = ia 16-slices, 16 b); block: 128 oa x 128 u, 8 warps (4m x 2n)
template<int KC, int S, int MLO, int SEL>
__global__ __launch_bounds__(256, 2) void conv_mma_kernel() {
    constexpr int UW   = 128 + KC - 1;
    constexpr int UWP0 = ((UW + 7) / 8) * 8;
    constexpr int UWP  = (UWP0 % 16 == 0) ? UWP0 + 8 : UWP0;   // stride ≡ 8 or 24 (mod 32)
    __shared__ uint32_t Ws[2][2][8][136];    // [stage][hi/lo][kp][oa]
    __shared__ uint32_t Zs[2][8][UWP];       // [hi/lo][kp][u]
    const int LQ = LLEN / S;
    int r  = blockIdx.x % S;
    int u0 = (blockIdx.x / S) * 128;
    int ia_q = blockIdx.y;                   // 16-ia slice (8 pairs)
    int b  = blockIdx.z;
    int tid = threadIdx.x;
    int w = tid >> 5, lane = tid & 31;
    int gid = lane >> 2, tig = lane & 3;
    int wm = w & 3, wn = w >> 2;

    const uint32_t* WH; const uint32_t* WL;
    if (SEL == 4)      { WH = g_WpH4; WL = g_WpL4; }
    else if (SEL == 2) { WH = g_WpH2; WL = g_WpL2; }
    else               { WH = g_WpH1; WL = g_WpL1; }

    // fill z smem (hi/lo bf16 pairs of rows 2kp, 2kp+1)
    const float* zbase = g_zq + ((size_t)b*NA + ia_q*16) * LLEN;
    for (int idx = tid; idx < 8*UWP; idx += 256) {
        int kp = idx / UWP, j = idx % UWP;
        int uq = u0 - MLO + j;
        bool valid = (uq >= 0) && (uq < LQ) && (j < UW);
        float v0 = valid ? zbase[(size_t)(2*kp)*LLEN + uq] : 0.f;
        float v1 = valid ? zbase[(size_t)(2*kp+1)*LLEN + uq] : 0.f;
        uint32_t h, l;
        split_pack(v0, v1, h, l);
        Zs[0][kp][j] = h;
        Zs[1][kp][j] = l;
    }

    float acc[2][8][4];
    #pragma unroll
    for (int i = 0; i < 2; i++)
        #pragma unroll
        for (int j = 0; j < 8; j++)
            #pragma unroll
            for (int q = 0; q < 4; q++) acc[i][j][q] = 0.f;

    // weight tile fill: 8 kp x 128 oa, contiguous 1024 u32 per array
    auto fillW = [&](int st, int mc) {
        size_t base = ((size_t)(r*KC + mc)*64 + ia_q*8) * 128;
        uint4 vh = ((const uint4*)(WH + base))[tid];
        uint4 vl = ((const uint4*)(WL + base))[tid];
        int kp = tid >> 5, c4 = (tid & 31) * 4;
        *(uint4*)&Ws[st][0][kp][c4] = vh;
        *(uint4*)&Ws[st][1][kp][c4] = vl;
    };

    fillW(0, 0);
    __syncthreads();

    for (int mc = 0; mc < KC; mc++) {
        int st = mc & 1;
        if (mc + 1 < KC) fillW((mc + 1) & 1, mc + 1);
        // A fragments (weights), hi and lo
        uint32_t ah[2][4], al[2][4];
        #pragma unroll
        for (int i = 0; i < 2; i++) {
            int m = wm*32 + i*16 + gid;
            ah[i][0] = Ws[st][0][tig  ][m];
            ah[i][1] = Ws[st][0][tig  ][m + 8];
            ah[i][2] = Ws[st][0][tig+4][m];
            ah[i][3] = Ws[st][0][tig+4][m + 8];
            al[i][0] = Ws[st][1][tig  ][m];
            al[i][1] = Ws[st][1][tig  ][m + 8];
            al[i][2] = Ws[st][1][tig+4][m];
            al[i][3] = Ws[st][1][tig+4][m + 8];
        }
        #pragma unroll
        for (int j = 0; j < 8; j++) {
            int un = wn*64 + j*8 + gid + mc;
            uint32_t bh0 = Zs[0][tig  ][un];
            uint32_t bh1 = Zs[0][tig+4][un];
            uint32_t bl0 = Zs[1][tig  ][un];
            uint32_t bl1 = Zs[1][tig+4][un];
            #pragma unroll
            for (int i = 0; i < 2; i++) {
                MMA_BF16(acc[i][j], ah[i], bh0, bh1);
                MMA_BF16(acc[i][j], ah[i], bl0, bl1);
                MMA_BF16(acc[i][j], al[i], bh0, bh1);
            }
        }
        __syncthreads();
    }

    // epilogue: C frag c0:(gid, 2tig) c1:(gid, 2tig+1) c2:(gid+8, 2tig) c3:(gid+8, 2tig+1)
    int oa_b = wm*32 + gid;
    #pragma unroll
    for (int i = 0; i < 2; i++) {
        float* d0 = g_rectotal + ((size_t)b*NA + oa_b + i*16)*LLEN + r;
        float* d1 = d0 + (size_t)8*LLEN;
        #pragma unroll
        for (int j = 0; j < 8; j++) {
            int u1 = u0 + wn*64 + j*8 + tig*2;
            atomicAdd(&d0[(size_t)S*u1],       acc[i][j][0]);
            atomicAdd(&d0[(size_t)S*(u1+1)],   acc[i][j][1]);
            atomicAdd(&d1[(size_t)S*u1],       acc[i][j][2]);
            atomicAdd(&d1[(size_t)S*(u1+1)],   acc[i][j][3]);
        }
    }
}

// ================= decoder =================
__global__ __launch_bounds__(256) void decoder_kernel(const float* __restrict__ dec_b,
                                                      float* __restrict__ out) {
    __shared__ float Wsm[4][3][64];
    __shared__ float zsm[4][130];
    int q0 = blockIdx.x * 128;
    int row0 = blockIdx.y * 64;
    int b = blockIdx.z;
    int tid = threadIdx.x, tx = tid & 15, ty = tid >> 4;
    float acc[4][8];
    #pragma unroll
    for (int m = 0; m < 4; m++)
        #pragma unroll
        for (int n = 0; n < 8; n++) acc[m][n] = 0.f;

    for (int na0 = 0; na0 < NA; na0 += 4) {
        __syncthreads();
        for (int i = tid; i < 768; i += 256) {
            int nl = i / 192, rem = i % 192, m = rem / 64, rl = rem % 64;
            Wsm[nl][m][rl] = g_WdT[((size_t)(na0+nl)*3 + m)*384 + row0 + rl];
        }
        for (int i = tid; i < 520; i += 256) {
            int nl = i / 130, j = i % 130;
            int q = q0 - 1 + j;
            zsm[nl][j] = (q >= 0 && q < LLEN) ? g_rectotal[((size_t)b*NA + na0 + nl)*LLEN + q] : 0.f;
        }
        __syncthreads();
        #pragma unroll
        for (int nl = 0; nl < 4; nl++) {
            float z[10];
            #pragma unroll
            for (int j = 0; j < 10; j++) z[j] = zsm[nl][ty*8 + j];
            #pragma unroll
            for (int m = 0; m < 3; m++) {
                float4 wv = *(const float4*)&Wsm[nl][m][tx*4];
                #pragma unroll
                for (int n = 0; n < 8; n++) {
                    float zz = z[n + m];
                    acc[0][n] += wv.x * zz; acc[1][n] += wv.y * zz;
                    acc[2][n] += wv.z * zz; acc[3][n] += wv.w * zz;
                }
            }
        }
    }
    int row = row0 + tx*4;
    int c = row >> 5, r0 = row & 31;
    float sd = g_std[b*CIN + c], mn = g_mean[b*CIN + c], bb = dec_b[c];
    float* ob = out + ((size_t)(b*CIN + c)) * TLEN;
    #pragma unroll
    for (int n = 0; n < 8; n++) {
        int q = q0 + ty*8 + n;
        if (q < 511) {
            float4 v;
            v.x = (acc[0][n] + bb) * sd + mn;
            v.y = (acc[1][n] + bb) * sd + mn;
            v.z = (acc[2][n] + bb) * sd + mn;
            v.w = (acc[3][n] + bb) * sd + mn;
            *(float4*)&ob[q*32 + r0] = v;
        }
    }
}

__global__ void finalize_kernel(float* __restrict__ out) {
    out[NOUT]     = 0.f;
    out[NOUT + 1] = 0.01f * (g_l1[0] / (16.f*128.f*128.f)
                           + g_l1[1] / (16.f*128.f*256.f)
                           + g_l1[2] / (16.f*128.f*512.f));
}

// ================= launch =================
extern "C" void kernel_launch(void* const* d_in, const int* in_sizes, int n_in,
                              void* d_out, int out_size) {
    const float* x   = (const float*)d_in[0];
    const float* w1  = (const float*)d_in[1];
    const float* b1  = (const float*)d_in[2];
    const float* w2  = (const float*)d_in[3];
    const float* b2  = (const float*)d_in[4];
    const float* scl = (const float*)d_in[5];
    const float* shp = (const float*)d_in[6];
    const float* dw  = (const float*)d_in[7];
    const float* db  = (const float*)d_in[8];
    float* out = (float*)d_out;

    fused_prep_kernel<<<NROWS + 32, 256>>>(x, w1, w2, shp, dw);           // 1
    fused_stem_kernel<<<1024, 256>>>(b1);                                 // 2
    conv1x1_pool4_pack_kernel<<<dim3(24, BATCH), 256>>>(b2, scl);         // 3 (conv + weight pack)
    conv_mma_kernel<17, 4, 8,  4><<<dim3(4, 8, BATCH), 256>>>();          // 4 (profiled)
    pool_kernel<<<BATCH*NA, 128>>>(2, 1);                                 // 5
    conv_mma_kernel<33, 2, 16, 2><<<dim3(4, 8, BATCH), 256>>>();          // 6
    pool_kernel<<<BATCH*NA, 128>>>(1, 2);                                 // 7
    conv_mma_kernel<64, 1, 31, 1><<<dim3(4, 8, BATCH), 256>>>();          // 8
    decoder_kernel<<<dim3(4, 6, BATCH), 256>>>(db, out);                  // 9
    if (out_size >= NOUT + 2) finalize_kernel<<<1, 1>>>(out);             // 10
}

// round 14
// speedup vs baseline: 2.4797x; 1.1036x over previous
#include <cuda_runtime.h>
#include <cuda_bf16.h>
#include <math.h>
#include <stdint.h>

// ---------------- problem constants ----------------
#define BATCH   16
#define CIN     12
#define TLEN    16352
#define ATOM    64
#define STRIDE  32
#define NA      128
#define LLEN    512
#define NROWS   (BATCH*CIN)
#define NOUT    (BATCH*CIN*TLEN)

// ---------------- scratch (device globals) ----------------
__device__ float g_mean[NROWS];
__device__ float g_std[NROWS];
__device__ float g_xnorm[(size_t)BATCH*CIN*TLEN];
__device__ float g_h[(size_t)BATCH*LLEN*64];
__device__ float g_zraw[(size_t)BATCH*NA*LLEN];
__device__ float g_zq[(size_t)BATCH*NA*LLEN];          // compact z_q, row stride 512
__device__ float g_rectotal[(size_t)BATCH*NA*LLEN];
__device__ float g_w1t[12*64*64];
__device__ float g_w2t[64*128];
__device__ float g_shpnT[(size_t)NA*ATOM*NA];          // [(ia*64+k)*128 + oa]
__device__ float g_Wc4[(size_t)4*128*17*128];          // [((r*128+ia)*17+mc)*128+oa]
__device__ float g_Wc2[(size_t)2*128*33*128];
__device__ float g_WdT[(size_t)NA*3*384];
__device__ float g_l1[3];
// packed bf16x2 hi/lo weight tiles: [((r*KC+mc)*64 + kp)*128 + oa], pair = (ia=2kp lo16, ia=2kp+1 hi16)
__device__ uint32_t g_WpH4[(size_t)4*17*64*128];
__device__ uint32_t g_WpL4[(size_t)4*17*64*128];
__device__ uint32_t g_WpH2[(size_t)2*33*64*128];
__device__ uint32_t g_WpL2[(size_t)2*33*64*128];
__device__ uint32_t g_WpH1[(size_t)1*64*64*128];
__device__ uint32_t g_WpL1[(size_t)1*64*64*128];

#define MMA_BF16(c, a, b0_, b1_) \
    asm volatile("mma.sync.aligned.m16n8k16.row.col.f32.bf16.bf16.f32 " \
        "{%0,%1,%2,%3}, {%4,%5,%6,%7}, {%8,%9}, {%0,%1,%2,%3};" \
        : "+f"((c)[0]), "+f"((c)[1]), "+f"((c)[2]), "+f"((c)[3]) \
        : "r"((a)[0]), "r"((a)[1]), "r"((a)[2]), "r"((a)[3]), "r"(b0_), "r"(b1_))

__device__ __forceinline__ void cp_async16(uint32_t s, const void* g) {
    asm volatile("cp.async.cg.shared.global [%0], [%1], 16;" :: "r"(s), "l"(g));
}
#define CP_COMMIT() asm volatile("cp.async.commit_group;" ::: "memory")
#define CP_WAIT0()  asm volatile("cp.async.wait_group 0;" ::: "memory")

__device__ __forceinline__ uint32_t pack_bf16x2(float v0, float v1) {
    __nv_bfloat16 h0 = __float2bfloat16(v0);
    __nv_bfloat16 h1 = __float2bfloat16(v1);
    return ((uint32_t)__bfloat16_as_ushort(h1) << 16) | (uint32_t)__bfloat16_as_ushort(h0);
}
__device__ __forceinline__ void split_pack(float v0, float v1, uint32_t& h, uint32_t& l) {
    __nv_bfloat16 h0 = __float2bfloat16(v0);
    __nv_bfloat16 h1 = __float2bfloat16(v1);
    float l0 = v0 - __bfloat162float(h0);
    float l1 = v1 - __bfloat162float(h1);
    h = ((uint32_t)__bfloat16_as_ushort(h1) << 16) | (uint32_t)__bfloat16_as_ushort(h0);
    l = pack_bf16x2(l0, l1);
}

// ================= L1: fused stats+norm + misc preps + rectotal zero =================
__global__ __launch_bounds__(256) void fused_prep_kernel(
    const float* __restrict__ x,  const float* __restrict__ w1,
    const float* __restrict__ w2, const float* __restrict__ shp,
    const float* __restrict__ dw)
{
    int bid = blockIdx.x, tid = threadIdx.x;
    if (bid < NROWS) {
        int row = bid;
        const float* p = x + (size_t)row * TLEN;
        float s = 0.f, s2 = 0.f;
        for (int i = tid; i < TLEN; i += 256) { float v = p[i]; s += v; s2 += v*v; }
        __shared__ float sh[256], sh2[256];
        sh[tid] = s; sh2[tid] = s2;
        __syncthreads();
        for (int st = 128; st > 0; st >>= 1) {
            if (tid < st) { sh[tid] += sh[tid+st]; sh2[tid] += sh2[tid+st]; }
            __syncthreads();
        }
        __shared__ float smean, sistd;
        if (tid == 0) {
            float mean = sh[0] / (float)TLEN;
            float var  = sh2[0] / (float)TLEN - mean * mean;
            float sd   = sqrtf(var + 1e-5f);
            g_mean[row] = mean; g_std[row] = sd;
            smean = mean; sistd = 1.f / sd;
        }
        __syncthreads();
        float mean = smean, istd = sistd;
        size_t base = (size_t)row * TLEN;
        for (int i = tid; i < TLEN; i += 256)
            g_xnorm[base + i] = (p[i] - mean) * istd;
    } else {
        int base = (bid - NROWS) * 256 + tid;   // 0..8191
        {
            float4 z4 = make_float4(0.f, 0.f, 0.f, 0.f);
            float4* rt4 = (float4*)g_rectotal;
            for (int i = base; i < (BATCH*NA*LLEN)/4; i += 8192) rt4[i] = z4;
        }
        for (int i = base; i < 64*768; i += 8192) {
            int o = i / 768, ck = i % 768;
            g_w1t[ck*64 + o] = w1[i];
        }
        for (int i = base; i < 128*64; i += 8192) {
            int a = i >> 6, o = i & 63;
            g_w2t[o*128 + a] = w2[i];
        }
        for (int i = base; i < 384*NA*3; i += 8192) {
            int row = i % 384; int rest = i / 384; int m = rest % 3; int na = rest / 3;
            int c = row >> 5, r = row & 31;
            int d = m - 1;
            int klo = 32*d + 31 - r; if (klo < 0) klo = 0;
            int khi = 32*d + 62 - r; if (khi > 63) khi = 63;
            float s = 0.f;
            const float* p = dw + ((size_t)c*NA + na) * ATOM;
            for (int k = klo; k <= khi; k++) s += p[k];
            g_WdT[((size_t)na*3 + m)*384 + row] = s;
        }
        for (int i = base; i < NA*NA; i += 8192) {
            int oa = i >> 7, ia = i & 127;
            const float* p = shp + ((size_t)oa*NA + ia) * ATOM;
            float s = 0.f;
            for (int k = 0; k < ATOM; k++) { float v = p[k]; s += v*v; }
            float inv = 1.f / fmaxf(sqrtf(s), 1e-8f);
            for (int k = 0; k < ATOM; k++)
                g_shpnT[((size_t)ia*ATOM + k)*NA + oa] = p[k] * inv;
        }
        if (base < 3) g_l1[base] = 0.f;
    }
}

// ================= L2: fused stem + collapsed-weight prep =================
__device__ __forceinline__ void wc_compute(float* gW, int S, int KC, int MLO, int i) {
    int oa = i & 127;
    int rest = i >> 7;
    int mc = rest % KC;
    int rest2 = rest / KC;
    int ia = rest2 & 127;
    int r  = rest2 >> 7;
    int m = mc - MLO;
    int klo = S*m + 31 - r;
    int khi = klo + S - 1;
    if (klo < 0) klo = 0;
    if (khi > 63) khi = 63;
    float s = 0.f;
    for (int k = klo; k <= khi; k++)
        s += g_shpnT[((size_t)ia*ATOM + k)*NA + oa];
    gW[i] = s;
}

__global__ __launch_bounds__(256) void fused_stem_kernel(const float* __restrict__ b1) {
    __shared__ float xw[12][576];
    int bid = blockIdx.x, tid = threadIdx.x;
    if (bid < 512) {
        int b = bid >> 5, l0 = (bid & 31) * 16;
        for (int j = tid; j < 12*576; j += 256) {
            int c = j / 576, jj = j % 576;
            int g = 32*l0 - 32 + jj;
            xw[c][jj] = (g >= 0 && g < TLEN) ? g_xnorm[((size_t)b*CIN + c)*TLEN + g] : 0.f;
        }
        __syncthreads();
        int o = tid & 63, lh = tid >> 6;
        float acc[4] = {0,0,0,0};
        for (int c = 0; c < 12; c++) {
            #pragma unroll 4
            for (int k = 0; k < 64; k++) {
                float w = g_w1t[(c*64 + k)*64 + o];
                #pragma unroll
                for (int i = 0; i < 4; i++)
                    acc[i] += w * xw[c][32*(lh*4 + i) + k];
            }
        }
        float bo = b1[o];
        #pragma unroll
        for (int i = 0; i < 4; i++) {
            int l = l0 + lh*4 + i;
            g_h[((size_t)b*LLEN + l)*64 + o] = fmaxf(acc[i] + bo, 0.f);
        }
    } else {
        int base = (bid - 512) * 256 + tid;      // 0..131071
        const int N4 = 4*128*17*128;
        const int N2 = 2*128*33*128;
        for (int i = base; i < N4; i += 512*256) wc_compute(g_Wc4, 4, 17, 8,  i);
        for (int i = base; i < N2; i += 512*256) wc_compute(g_Wc2, 2, 33, 16, i);
    }
}

// ================= L3: 1x1 conv + fused s=4 pool + l1[0] + bf16 weight pack =================
__global__ __launch_bounds__(256) void conv1x1_pool4_pack_kernel(const float* __restrict__ b2,
                                                                 const float* __restrict__ scale) {
    __shared__ float hsm[64][64];
    __shared__ float w2sm[64][128];
    int bx = blockIdx.x, b = blockIdx.y;
    int tid = threadIdx.x;
    if (bx >= 8) {
        const int PN4 = 4*17*64*128;
        const int PN2 = 2*33*64*128;
        const int PN1 = 64*64*128;
        int gtid = ((bx - 8) + b * 16) * 256 + tid;
        for (int idx = gtid; idx < PN4 + PN2 + PN1; idx += 256*256) {
            int seg, li;
            if (idx < PN4) { seg = 0; li = idx; }
            else if (idx < PN4 + PN2) { seg = 1; li = idx - PN4; }
            else { seg = 2; li = idx - PN4 - PN2; }
            int KC = (seg == 0) ? 17 : (seg == 1 ? 33 : 64);
            int oa = li & 127;
            int t  = li >> 7;
            int kp = t & 63;
            int t2 = t >> 6;
            int mc = t2 % KC;
            int r  = t2 / KC;
            int ia0 = kp * 2;
            float v0, v1;
            if (seg == 0) {
                v0 = g_Wc4[(((size_t)r*128 + ia0    )*17 + mc)*128 + oa];
                v1 = g_Wc4[(((size_t)r*128 + ia0 + 1)*17 + mc)*128 + oa];
            } else if (seg == 1) {
                v0 = g_Wc2[(((size_t)r*128 + ia0    )*33 + mc)*128 + oa];
                v1 = g_Wc2[(((size_t)r*128 + ia0 + 1)*33 + mc)*128 + oa];
            } else {
                v0 = g_shpnT[((size_t)(ia0    )*64 + mc)*128 + oa];
                v1 = g_shpnT[((size_t)(ia0 + 1)*64 + mc)*128 + oa];
            }
            uint32_t h, l;
            split_pack(v0, v1, h, l);
            if (seg == 0)      { g_WpH4[li] = h; g_WpL4[li] = l; }
            else if (seg == 1) { g_WpH2[li] = h; g_WpL2[li] = l; }
            else               { g_WpH1[li] = h; g_WpL1[li] = l; }
        }
        return;
    }
    int l0 = bx * 64;
    for (int i = tid; i < 4096; i += 256) hsm[i >> 6][i & 63] = g_h[((size_t)b*LLEN + l0)*64 + i];
    for (int i = tid; i < 8192; i += 256) w2sm[i >> 7][i & 127] = g_w2t[i];
    __syncthreads();
    int tx = tid & 31, ty = tid >> 5;
    float acc[4][8];
    #pragma unroll
    for (int m = 0; m < 4; m++)
        #pragma unroll
        for (int n = 0; n < 8; n++) acc[m][n] = 0.f;
    for (int o = 0; o < 64; o++) {
        float4 wv = *(const float4*)&w2sm[o][tx*4];
        #pragma unroll
        for (int n = 0; n < 8; n++) {
            float hv = hsm[ty*8 + n][o];
            acc[0][n] += wv.x * hv; acc[1][n] += wv.y * hv;
            acc[2][n] += wv.z * hv; acc[3][n] += wv.w * hv;
        }
    }
    float sc = scale[0];
    float l1loc = 0.f;
    #pragma unroll
    for (int m = 0; m < 4; m++) {
        int a = tx*4 + m;
        float bb = b2[a];
        size_t rowb = ((size_t)b*NA + a)*LLEN;
        #pragma unroll
        for (int n = 0; n < 8; n++) {
            float v = (acc[m][n] + bb) * sc;
            acc[m][n] = v;
            g_zraw[rowb + l0 + ty*8 + n] = v;
        }
        #pragma unroll
        for (int h = 0; h < 2; h++) {
            float zq = 0.25f * (acc[m][4*h] + acc[m][4*h+1] + acc[m][4*h+2] + acc[m][4*h+3]);
            g_zq[rowb + l0/4 + 2*ty + h] = zq;
            l1loc += fabsf(zq);
        }
    }
    __syncthreads();
    float* red = &hsm[0][0];
    red[tid] = l1loc;
    __syncthreads();
    for (int st = 128; st > 0; st >>= 1) {
        if (tid < st) red[tid] += red[tid + st];
        __syncthreads();
    }
    if (tid == 0) atomicAdd(&g_l1[0], red[0]);
}

// ================= pool (scales 2, 1) =================
__global__ __launch_bounds__(128) void pool_kernel(int s, int idx) {
    int row = blockIdx.x;
    size_t base = (size_t)row * LLEN;
    int nq = LLEN / s;
    float inv = 1.f / (float)s;
    float local = 0.f;
    for (int j = threadIdx.x; j < nq; j += 128) {
        int t0 = j * s;
        float sum = 0.f;
        for (int t = 0; t < s; t++) sum += g_zraw[base + t0 + t] - g_rectotal[base + t0 + t];
        float zq = sum * inv;
        local += fabsf(zq);
        g_zq[base + j] = zq;
    }
    __shared__ float red[128];
    red[threadIdx.x] = local;
    __syncthreads();
    for (int st = 64; st > 0; st >>= 1) {
        if (threadIdx.x < st) red[threadIdx.x] += red[threadIdx.x + st];
        __syncthreads();
    }
    if (threadIdx.x == 0) atomicAdd(&g_l1[idx], red[0]);
}

// ================= tensor-core collapsed conv (mma.sync bf16 hi/lo split) =================
// D[oa, S*u+r] += sum_{ia,mc} Wc[r][ia][mc][oa] * zq[ia][u+mc-MLO]
// grid (8 = (LQ/64)*S, 8 = ia 16-slices, 16 b); block: 128 oa x 64 u, 8 warps (4m x 2n)
// cp.async double-buffered weight fill, one barrier per tap.
template<int KC, int S, int MLO, int SEL>
__global__ __launch_bounds__(256, 3) void conv_mma_kernel() {
    constexpr int UW   = 64 + KC - 1;
    constexpr int UWP0 = ((UW + 7) / 8) * 8;
    constexpr int UWP  = (UWP0 % 16 == 0) ? UWP0 + 8 : UWP0;   // stride ≡ 8 or 24 (mod 32)
    __shared__ uint32_t Ws[2][2][8][136];    // [stage][hi/lo][kp][oa]
    __shared__ uint32_t Zs[2][8][UWP];       // [hi/lo][kp][u]
    const int LQ = LLEN / S;
    int r  = blockIdx.x % S;
    int u0 = (blockIdx.x / S) * 64;
    int ia_q = blockIdx.y;                   // 16-ia slice (8 pairs)
    int b  = blockIdx.z;
    int tid = threadIdx.x;
    int w = tid >> 5, lane = tid & 31;
    int gid = lane >> 2, tig = lane & 3;
    int wm = w & 3, wn = w >> 2;

    const uint32_t* WH; const uint32_t* WL;
    if (SEL == 4)      { WH = g_WpH4; WL = g_WpL4; }
    else if (SEL == 2) { WH = g_WpH2; WL = g_WpL2; }
    else               { WH = g_WpH1; WL = g_WpL1; }

    // fill z smem (hi/lo bf16 pairs of rows 2kp, 2kp+1)
    const float* zbase = g_zq + ((size_t)b*NA + ia_q*16) * LLEN;
    for (int idx = tid; idx < 8*UWP; idx += 256) {
        int kp = idx / UWP, j = idx % UWP;
        int uq = u0 - MLO + j;
        bool valid = (uq >= 0) && (uq < LQ) && (j < UW);
        float v0 = valid ? zbase[(size_t)(2*kp)*LLEN + uq] : 0.f;
        float v1 = valid ? zbase[(size_t)(2*kp+1)*LLEN + uq] : 0.f;
        uint32_t h, l;
        split_pack(v0, v1, h, l);
        Zs[0][kp][j] = h;
        Zs[1][kp][j] = l;
    }

    float acc[2][4][4];
    #pragma unroll
    for (int i = 0; i < 2; i++)
        #pragma unroll
        for (int j = 0; j < 4; j++)
            #pragma unroll
            for (int q = 0; q < 4; q++) acc[i][j][q] = 0.f;

    // async weight tile fill: 8 kp x 128 oa per hi/lo, one 16B chunk per thread each
    int fkp = tid >> 5, fc4 = (tid & 31) * 4;
    auto fillW = [&](int st, int mc) {
        size_t base = ((size_t)(r*KC + mc)*64 + ia_q*8) * 128;
        uint32_t dh = (uint32_t)__cvta_generic_to_shared(&Ws[st][0][fkp][fc4]);
        uint32_t dl = (uint32_t)__cvta_generic_to_shared(&Ws[st][1][fkp][fc4]);
        cp_async16(dh, WH + base + (size_t)tid*4);
        cp_async16(dl, WL + base + (size_t)tid*4);
        CP_COMMIT();
    };

    fillW(0, 0);

    for (int mc = 0; mc < KC; mc++) {
        int st = mc & 1;
        CP_WAIT0();
        __syncthreads();                 // stage st ready; all warps done reading stage st (tap mc-2)
        if (mc + 1 < KC) fillW((mc + 1) & 1, mc + 1);
        // A fragments (weights), hi and lo
        uint32_t ah[2][4], al[2][4];
        #pragma unroll
        for (int i = 0; i < 2; i++) {
            int m = wm*32 + i*16 + gid;
            ah[i][0] = Ws[st][0][tig  ][m];
            ah[i][1] = Ws[st][0][tig  ][m + 8];
            ah[i][2] = Ws[st][0][tig+4][m];
            ah[i][3] = Ws[st][0][tig+4][m + 8];
            al[i][0] = Ws[st][1][tig  ][m];
            al[i][1] = Ws[st][1][tig  ][m + 8];
            al[i][2] = Ws[st][1][tig+4][m];
            al[i][3] = Ws[st][1][tig+4][m + 8];
        }
        #pragma unroll
        for (int j = 0; j < 4; j++) {
            int un = wn*32 + j*8 + gid + mc;
            uint32_t bh0 = Zs[0][tig  ][un];
            uint32_t bh1 = Zs[0][tig+4][un];
            uint32_t bl0 = Zs[1][tig  ][un];
            uint32_t bl1 = Zs[1][tig+4][un];
            #pragma unroll
            for (int i = 0; i < 2; i++) {
                MMA_BF16(acc[i][j], ah[i], bh0, bh1);
                MMA_BF16(acc[i][j], ah[i], bl0, bl1);
                MMA_BF16(acc[i][j], al[i], bh0, bh1);
            }
        }
        __syncthreads();                 // all warps done with stage st before it is refilled next iter
    }

    // epilogue: C frag c0:(gid, 2tig) c1:(gid, 2tig+1) c2:(gid+8, 2tig) c3:(gid+8, 2tig+1)
    int oa_b = wm*32 + gid;
    #pragma unroll
    for (int i = 0; i < 2; i++) {
        float* d0 = g_rectotal + ((size_t)b*NA + oa_b + i*16)*LLEN + r;
        float* d1 = d0 + (size_t)8*LLEN;
        #pragma unroll
        for (int j = 0; j < 4; j++) {
            int u1 = u0 + wn*32 + j*8 + tig*2;
            atomicAdd(&d0[(size_t)S*u1],       acc[i][j][0]);
            atomicAdd(&d0[(size_t)S*(u1+1)],   acc[i][j][1]);
            atomicAdd(&d1[(size_t)S*u1],       acc[i][j][2]);
            atomicAdd(&d1[(size_t)S*(u1+1)],   acc[i][j][3]);
        }
    }
}

// ================= decoder =================
__global__ __launch_bounds__(256) void decoder_kernel(const float* __restrict__ dec_b,
                                                      float* __restrict__ out) {
    __shared__ float Wsm[4][3][64];
    __shared__ float zsm[4][130];
    int q0 = blockIdx.x * 128;
    int row0 = blockIdx.y * 64;
    int b = blockIdx.z;
    int tid = threadIdx.x, tx = tid & 15, ty = tid >> 4;
    float acc[4][8];
    #pragma unroll
    for (int m = 0; m < 4; m++)
        #pragma unroll
        for (int n = 0; n < 8; n++) acc[m][n] = 0.f;

    for (int na0 = 0; na0 < NA; na0 += 4) {
        __syncthreads();
        for (int i = tid; i < 768; i += 256) {
            int nl = i / 192, rem = i % 192, m = rem / 64, rl = rem % 64;
            Wsm[nl][m][rl] = g_WdT[((size_t)(na0+nl)*3 + m)*384 + row0 + rl];
        }
        for (int i = tid; i < 520; i += 256) {
            int nl = i / 130, j = i % 130;
            int q = q0 - 1 + j;
            zsm[nl][j] = (q >= 0 && q < LLEN) ? g_rectotal[((size_t)b*NA + na0 + nl)*LLEN + q] : 0.f;
        }
        __syncthreads();
        #pragma unroll
        for (int nl = 0; nl < 4; nl++) {
            float z[10];
            #pragma unroll
            for (int j = 0; j < 10; j++) z[j] = zsm[nl][ty*8 + j];
            #pragma unroll
            for (int m = 0; m < 3; m++) {
                float4 wv = *(const float4*)&Wsm[nl][m][tx*4];
                #pragma unroll
                for (int n = 0; n < 8; n++) {
                    float zz = z[n + m];
                    acc[0][n] += wv.x * zz; acc[1][n] += wv.y * zz;
                    acc[2][n] += wv.z * zz; acc[3][n] += wv.w * zz;
                }
            }
        }
    }
    int row = row0 + tx*4;
    int c = row >> 5, r0 = row & 31;
    float sd = g_std[b*CIN + c], mn = g_mean[b*CIN + c], bb = dec_b[c];
    float* ob = out + ((size_t)(b*CIN + c)) * TLEN;
    #pragma unroll
    for (int n = 0; n < 8; n++) {
        int q = q0 + ty*8 + n;
        if (q < 511) {
            float4 v;
            v.x = (acc[0][n] + bb) * sd + mn;
            v.y = (acc[1][n] + bb) * sd + mn;
            v.z = (acc[2][n] + bb) * sd + mn;
            v.w = (acc[3][n] + bb) * sd + mn;
            *(float4*)&ob[q*32 + r0] = v;
        }
    }
}

__global__ void finalize_kernel(float* __restrict__ out) {
    out[NOUT]     = 0.f;
    out[NOUT + 1] = 0.01f * (g_l1[0] / (16.f*128.f*128.f)
                           + g_l1[1] / (16.f*128.f*256.f)
                           + g_l1[2] / (16.f*128.f*512.f));
}

// ================= launch =================
extern "C" void kernel_launch(void* const* d_in, const int* in_sizes, int n_in,
                              void* d_out, int out_size) {
    const float* x   = (const float*)d_in[0];
    const float* w1  = (const float*)d_in[1];
    const float* b1  = (const float*)d_in[2];
    const float* w2  = (const float*)d_in[3];
    const float* b2  = (const float*)d_in[4];
    const float* scl = (const float*)d_in[5];
    const float* shp = (const float*)d_in[6];
    const float* dw  = (const float*)d_in[7];
    const float* db  = (const float*)d_in[8];
    float* out = (float*)d_out;

    fused_prep_kernel<<<NROWS + 32, 256>>>(x, w1, w2, shp, dw);           // 1
    fused_stem_kernel<<<1024, 256>>>(b1);                                 // 2
    conv1x1_pool4_pack_kernel<<<dim3(24, BATCH), 256>>>(b2, scl);         // 3 (conv + weight pack)
    conv_mma_kernel<17, 4, 8,  4><<<dim3(8, 8, BATCH), 256>>>();          // 4 (profiled)
    pool_kernel<<<BATCH*NA, 128>>>(2, 1);                                 // 5
    conv_mma_kernel<33, 2, 16, 2><<<dim3(8, 8, BATCH), 256>>>();          // 6
    pool_kernel<<<BATCH*NA, 128>>>(1, 2);                                 // 7
    conv_mma_kernel<64, 1, 31, 1><<<dim3(8, 8, BATCH), 256>>>();          // 8
    decoder_kernel<<<dim3(4, 6, BATCH), 256>>>(db, out);                  // 9
    if (out_size >= NOUT + 2) finalize_kernel<<<1, 1>>>(out);             // 10
}